// round 1
// baseline (speedup 1.0000x reference)
#include <cuda_runtime.h>
#include <math.h>

#define TINV 14.2857142857142857f  /* 1 / 0.07 */

// -------- scratch (no allocations allowed) --------
static __device__ float g_act0[4096 * 2048];   // 32 MB
static __device__ float g_act1[4096 * 2048];   // 32 MB
static __device__ float g_feat[8192 * 128];    // 4 MB  (rows 0..4095 = view1, 4096..8191 = view2)
static __device__ float g_pos[8192];
static __device__ float g_S[8192];

// ================= SGEMM 128x128x8, 256 thr, 8x8 micro =================
// C[M,N] = A[M,K] @ B[K,N] + bias[N], optional ReLU. Row-major everywhere.
template <bool RELU>
__global__ __launch_bounds__(256) void sgemm128(
    const float* __restrict__ A, const float* __restrict__ B,
    const float* __restrict__ bias, float* __restrict__ C,
    int M, int N, int K)
{
    __shared__ float As[8][128];
    __shared__ float Bs[8][128];

    const int tid = threadIdx.x;
    const int tx = tid & 15;
    const int ty = tid >> 4;
    const int row0 = blockIdx.y * 128;
    const int col0 = blockIdx.x * 128;

    const int arow = tid >> 1;          // 0..127
    const int ak   = (tid & 1) << 2;    // 0 or 4
    const int bk   = tid >> 5;          // 0..7
    const int bcol = (tid & 31) << 2;   // 0..124

    const float* Ap = A + (long)(row0 + arow) * K + ak;
    const float* Bp = B + (long)bk * N + col0 + bcol;

    float acc[8][8];
#pragma unroll
    for (int i = 0; i < 8; i++)
#pragma unroll
        for (int j = 0; j < 8; j++) acc[i][j] = 0.f;

    for (int k0 = 0; k0 < K; k0 += 8) {
        float4 av = *(const float4*)(Ap + k0);
        float4 bv = *(const float4*)(Bp + (long)k0 * N);
        As[ak + 0][arow] = av.x;
        As[ak + 1][arow] = av.y;
        As[ak + 2][arow] = av.z;
        As[ak + 3][arow] = av.w;
        *(float4*)&Bs[bk][bcol] = bv;
        __syncthreads();
#pragma unroll
        for (int k = 0; k < 8; k++) {
            float a[8], b[8];
            *(float4*)&a[0] = *(const float4*)&As[k][ty * 8];
            *(float4*)&a[4] = *(const float4*)&As[k][ty * 8 + 4];
            *(float4*)&b[0] = *(const float4*)&Bs[k][tx * 8];
            *(float4*)&b[4] = *(const float4*)&Bs[k][tx * 8 + 4];
#pragma unroll
            for (int i = 0; i < 8; i++)
#pragma unroll
                for (int j = 0; j < 8; j++)
                    acc[i][j] = fmaf(a[i], b[j], acc[i][j]);
        }
        __syncthreads();
    }

#pragma unroll
    for (int i = 0; i < 8; i++) {
        int r = row0 + ty * 8 + i;
#pragma unroll
        for (int j0 = 0; j0 < 8; j0 += 4) {
            int c = col0 + tx * 8 + j0;
            float4 v;
            v.x = acc[i][j0 + 0] + bias[c + 0];
            v.y = acc[i][j0 + 1] + bias[c + 1];
            v.z = acc[i][j0 + 2] + bias[c + 2];
            v.w = acc[i][j0 + 3] + bias[c + 3];
            if (RELU) {
                v.x = fmaxf(v.x, 0.f); v.y = fmaxf(v.y, 0.f);
                v.z = fmaxf(v.z, 0.f); v.w = fmaxf(v.w, 0.f);
            }
            *(float4*)&C[(long)r * N + c] = v;
        }
    }
}

// ================= SGEMM 64x64x16, 256 thr, 4x4 micro (for N=128) =================
__global__ __launch_bounds__(256) void sgemm64(
    const float* __restrict__ A, const float* __restrict__ B,
    const float* __restrict__ bias, float* __restrict__ C,
    int M, int N, int K)
{
    __shared__ float As[16][64];
    __shared__ float Bs[16][64];

    const int tid = threadIdx.x;
    const int tx = tid & 15;
    const int ty = tid >> 4;
    const int row0 = blockIdx.y * 64;
    const int col0 = blockIdx.x * 64;

    const int arow = tid >> 2;          // 0..63
    const int ak   = (tid & 3) << 2;    // 0..12
    const int bk   = tid >> 4;          // 0..15
    const int bcol = (tid & 15) << 2;   // 0..60

    const float* Ap = A + (long)(row0 + arow) * K + ak;
    const float* Bp = B + (long)bk * N + col0 + bcol;

    float acc[4][4];
#pragma unroll
    for (int i = 0; i < 4; i++)
#pragma unroll
        for (int j = 0; j < 4; j++) acc[i][j] = 0.f;

    for (int k0 = 0; k0 < K; k0 += 16) {
        float4 av = *(const float4*)(Ap + k0);
        float4 bv = *(const float4*)(Bp + (long)k0 * N);
        As[ak + 0][arow] = av.x;
        As[ak + 1][arow] = av.y;
        As[ak + 2][arow] = av.z;
        As[ak + 3][arow] = av.w;
        *(float4*)&Bs[bk][bcol] = bv;
        __syncthreads();
#pragma unroll
        for (int k = 0; k < 16; k++) {
            float a[4], b[4];
            *(float4*)&a[0] = *(const float4*)&As[k][ty * 4];
            *(float4*)&b[0] = *(const float4*)&Bs[k][tx * 4];
#pragma unroll
            for (int i = 0; i < 4; i++)
#pragma unroll
                for (int j = 0; j < 4; j++)
                    acc[i][j] = fmaf(a[i], b[j], acc[i][j]);
        }
        __syncthreads();
    }

#pragma unroll
    for (int i = 0; i < 4; i++) {
        int r = row0 + ty * 4 + i;
        int c = col0 + tx * 4;
        float4 v;
        v.x = acc[i][0] + bias[c + 0];
        v.y = acc[i][1] + bias[c + 1];
        v.z = acc[i][2] + bias[c + 2];
        v.w = acc[i][3] + bias[c + 3];
        *(float4*)&C[(long)r * N + c] = v;
    }
}

// ================= row L2-normalize (one warp per 128-float row) =================
__global__ __launch_bounds__(256) void normalize_kernel(float* __restrict__ f)
{
    int row  = blockIdx.x * 8 + (threadIdx.x >> 5);
    int lane = threadIdx.x & 31;
    float4 v = ((const float4*)f)[row * 32 + lane];
    float s = v.x * v.x + v.y * v.y + v.z * v.z + v.w * v.w;
#pragma unroll
    for (int o = 16; o; o >>= 1) s += __shfl_xor_sync(0xffffffffu, s, o);
    float r = rsqrtf(s);
    v.x *= r; v.y *= r; v.z *= r; v.w *= r;
    ((float4*)f)[row * 32 + lane] = v;
}

// ================= positive-pair similarity + zero S =================
__global__ __launch_bounds__(256) void pos_kernel(
    const float* __restrict__ f, float* __restrict__ pos, float* __restrict__ S)
{
    int row  = blockIdx.x * 8 + (threadIdx.x >> 5);
    int lane = threadIdx.x & 31;
    int partner = (row + 4096) & 8191;
    float4 a = ((const float4*)f)[row * 32 + lane];
    float4 b = ((const float4*)f)[partner * 32 + lane];
    float s = a.x * b.x + a.y * b.y + a.z * b.z + a.w * b.w;
#pragma unroll
    for (int o = 16; o; o >>= 1) s += __shfl_xor_sync(0xffffffffu, s, o);
    if (lane == 0) { pos[row] = s * TINV; S[row] = 0.f; }
}

// ================= fused sim + sum-of-exp =================
// grid = (2 column halves, 128 row tiles of 64). Block: 128 thr, 8x8 micro,
// row tile 64 x col tile 128, k = 128. smem: rowsT[128][64] + colsT[128][128].
// S[i] += sum_{j in half, j != i} exp(sim_ij - 1/T). Exactly 2 atomic adds per
// row -> commutative -> deterministic.
__global__ __launch_bounds__(128) void loss_kernel(
    const float* __restrict__ f, float* __restrict__ S)
{
    extern __shared__ float sm[];
    float* rowsT = sm;            // [k][row]  128*64
    float* colsT = sm + 128 * 64; // [k][col]  128*128

    const int tid = threadIdx.x;
    const int tx = tid & 15;      // 16 col groups of 8
    const int ty = tid >> 4;      // 8 row groups of 8
    const int r0 = blockIdx.y * 64;
    const int cbase = blockIdx.x * 4096;

    // load 64 rows, transposed to k-major
    for (int q = tid; q < 64 * 32; q += 128) {
        int r  = q & 63;
        int k4 = q >> 6;
        float4 v = ((const float4*)f)[(r0 + r) * 32 + k4];
        rowsT[(k4 * 4 + 0) * 64 + r] = v.x;
        rowsT[(k4 * 4 + 1) * 64 + r] = v.y;
        rowsT[(k4 * 4 + 2) * 64 + r] = v.z;
        rowsT[(k4 * 4 + 3) * 64 + r] = v.w;
    }

    float accS[8];
#pragma unroll
    for (int i = 0; i < 8; i++) accS[i] = 0.f;

    for (int ct = 0; ct < 32; ct++) {
        int c0 = cbase + ct * 128;
        __syncthreads();
        for (int q = tid; q < 128 * 32; q += 128) {
            int c  = q & 127;
            int k4 = q >> 7;
            float4 v = ((const float4*)f)[(c0 + c) * 32 + k4];
            colsT[(k4 * 4 + 0) * 128 + c] = v.x;
            colsT[(k4 * 4 + 1) * 128 + c] = v.y;
            colsT[(k4 * 4 + 2) * 128 + c] = v.z;
            colsT[(k4 * 4 + 3) * 128 + c] = v.w;
        }
        __syncthreads();

        float dotv[8][8];
#pragma unroll
        for (int i = 0; i < 8; i++)
#pragma unroll
            for (int j = 0; j < 8; j++) dotv[i][j] = 0.f;

#pragma unroll 4
        for (int k = 0; k < 128; k++) {
            float a[8], b[8];
            *(float4*)&a[0] = *(const float4*)&rowsT[k * 64 + ty * 8];
            *(float4*)&a[4] = *(const float4*)&rowsT[k * 64 + ty * 8 + 4];
            *(float4*)&b[0] = *(const float4*)&colsT[k * 128 + tx * 8];
            *(float4*)&b[4] = *(const float4*)&colsT[k * 128 + tx * 8 + 4];
#pragma unroll
            for (int i = 0; i < 8; i++)
#pragma unroll
                for (int j = 0; j < 8; j++)
                    dotv[i][j] = fmaf(a[i], b[j], dotv[i][j]);
        }

#pragma unroll
        for (int i = 0; i < 8; i++) {
            int gi = r0 + ty * 8 + i;
#pragma unroll
            for (int j = 0; j < 8; j++) {
                int gj = c0 + tx * 8 + j;
                float e = __expf(dotv[i][j] * TINV - TINV);
                accS[i] += (gi != gj) ? e : 0.f;
            }
        }
    }

    // per-row cross-thread reduction (16 tx lanes per row) via smem reuse
    __syncthreads();
#pragma unroll
    for (int i = 0; i < 8; i++)
        colsT[(ty * 8 + i) * 16 + tx] = accS[i];
    __syncthreads();
    if (tid < 64) {
        float s = 0.f;
#pragma unroll
        for (int t = 0; t < 16; t++) s += colsT[tid * 16 + t];
        atomicAdd(&S[r0 + tid], s);
    }
}

// ================= final deterministic reduction =================
__global__ __launch_bounds__(256) void final_kernel(
    const float* __restrict__ S, const float* __restrict__ pos,
    float* __restrict__ out)
{
    __shared__ float sm[256];
    float v = 0.f;
    for (int i = threadIdx.x; i < 8192; i += 256)
        v += TINV + logf(S[i]) - pos[i];
    sm[threadIdx.x] = v;
    __syncthreads();
    for (int o = 128; o; o >>= 1) {
        if (threadIdx.x < o) sm[threadIdx.x] += sm[threadIdx.x + o];
        __syncthreads();
    }
    if (threadIdx.x == 0) out[0] = sm[0] * (1.0f / 8192.0f);
}

// ================= launch =================
extern "C" void kernel_launch(void* const* d_in, const int* in_sizes, int n_in,
                              void* d_out, int out_size)
{
    const float* x[2] = {(const float*)d_in[0], (const float*)d_in[1]};
    const float* W0 = (const float*)d_in[2];
    const float* b0 = (const float*)d_in[3];
    const float* W1 = (const float*)d_in[4];
    const float* b1 = (const float*)d_in[5];
    const float* W2 = (const float*)d_in[6];
    const float* b2 = (const float*)d_in[7];
    float* out = (float*)d_out;

    float *act0, *act1, *feat, *pos, *S;
    cudaGetSymbolAddress((void**)&act0, g_act0);
    cudaGetSymbolAddress((void**)&act1, g_act1);
    cudaGetSymbolAddress((void**)&feat, g_feat);
    cudaGetSymbolAddress((void**)&pos, g_pos);
    cudaGetSymbolAddress((void**)&S, g_S);

    cudaFuncSetAttribute(loss_kernel,
                         cudaFuncAttributeMaxDynamicSharedMemorySize, 98304);

    dim3 gBig(2048 / 128, 4096 / 128);   // (16, 32)
    dim3 gSmall(128 / 64, 4096 / 64);    // (2, 64)

    for (int v = 0; v < 2; v++) {
        sgemm128<true ><<<gBig, 256>>>(x[v], W0, b0, act0, 4096, 2048, 2048);
        sgemm128<false><<<gBig, 256>>>(act0, W1, b1, act1, 4096, 2048, 2048);
        sgemm64<<<gSmall, 256>>>(act1, W2, b2, feat + (long)v * 4096 * 128,
                                 4096, 128, 2048);
    }
    normalize_kernel<<<1024, 256>>>(feat);
    pos_kernel<<<1024, 256>>>(feat, pos, S);
    loss_kernel<<<dim3(2, 128), 128, 98304>>>(feat, S);
    final_kernel<<<1, 256>>>(S, pos, out);
}

// round 3
// speedup vs baseline: 1.1614x; 1.1614x over previous
#include <cuda_runtime.h>
#include <stdint.h>
#include <math.h>

#define TINV 14.2857142857142857f  /* 1 / 0.07 */

// -------- scratch (no allocations allowed) --------
static __device__ float g_act0[4096 * 2048];   // 32 MB
static __device__ float g_act1[4096 * 2048];   // 32 MB
static __device__ float g_feat[8192 * 128];    // 4 MB
static __device__ float g_pos[8192];
static __device__ float g_S[8192];

__device__ __forceinline__ void cp_async16(unsigned int saddr, const void* gptr) {
    asm volatile("cp.async.ca.shared.global [%0], [%1], 16;" :: "r"(saddr), "l"(gptr));
}
__device__ __forceinline__ void cp_commit() {
    asm volatile("cp.async.commit_group;");
}
__device__ __forceinline__ void cp_wait0() {
    asm volatile("cp.async.wait_group 0;");
}

// ================= SGEMM 128x128x16, 256 thr, 8x8 micro, double-buffered ======
// Conflict-free fragments: a = {As[k][ty*4], As[k][ty*4+64]},
//                          b = {Bs[k][tx*4], Bs[k][tx*4+64]}.
// Thread (tx,ty) owns rows {ty*4+i, 64+ty*4+i}, cols {tx*4+j, 64+tx*4+j}.
template <bool RELU>
__global__ __launch_bounds__(256, 2) void sgemm128(
    const float* __restrict__ A, const float* __restrict__ B,
    const float* __restrict__ bias, float* __restrict__ C,
    int M, int N, int K)
{
    __shared__ float As[2][16][128];
    __shared__ float Bs[2][16][128];

    const int tid = threadIdx.x;
    const int tx = tid & 15;
    const int ty = tid >> 4;
    const int row0 = blockIdx.y * 128;
    const int col0 = blockIdx.x * 128;

    // A staging: 128 rows x 16 k, 8 floats/thread (one row, k-range of 8)
    const int arow = tid >> 1;          // 0..127
    const int ak   = (tid & 1) << 3;    // 0 or 8
    // B staging: 16 rows x 128 cols via cp.async, 2 x 16B per thread
    const int bk   = tid >> 5;          // 0..7 (rows bk and bk+8)
    const int bcol = (tid & 31) << 2;   // 0..124

    const float* Aptr = A + (long)(row0 + arow) * K + ak;
    const float* Bptr = B + (long)bk * N + col0 + bcol;

    unsigned int sB0a = (unsigned int)__cvta_generic_to_shared(&Bs[0][bk][bcol]);
    unsigned int sB0b = (unsigned int)__cvta_generic_to_shared(&Bs[0][bk + 8][bcol]);
    const unsigned int bufStride = 16 * 128 * 4;

    const int NKT = K >> 4;

    // ---- prologue: tile 0 ----
    float4 av0 = *(const float4*)(Aptr);
    float4 av1 = *(const float4*)(Aptr + 4);
    cp_async16(sB0a, Bptr);
    cp_async16(sB0b, Bptr + 8 * N);
    cp_commit();
    As[0][ak + 0][arow] = av0.x; As[0][ak + 1][arow] = av0.y;
    As[0][ak + 2][arow] = av0.z; As[0][ak + 3][arow] = av0.w;
    As[0][ak + 4][arow] = av1.x; As[0][ak + 5][arow] = av1.y;
    As[0][ak + 6][arow] = av1.z; As[0][ak + 7][arow] = av1.w;
    cp_wait0();
    __syncthreads();

    float acc[8][8];
#pragma unroll
    for (int i = 0; i < 8; i++)
#pragma unroll
        for (int j = 0; j < 8; j++) acc[i][j] = 0.f;

    for (int kt = 0; kt < NKT; kt++) {
        const int cur = kt & 1;
        const int nxt = cur ^ 1;
        const bool more = (kt + 1 < NKT);

        if (more) {
            const float* ap = Aptr + (kt + 1) * 16;
            av0 = *(const float4*)ap;
            av1 = *(const float4*)(ap + 4);
            const float* bp = Bptr + (long)(kt + 1) * 16 * N;
            cp_async16(sB0a + nxt * bufStride, bp);
            cp_async16(sB0b + nxt * bufStride, bp + 8 * N);
            cp_commit();
        }

#pragma unroll
        for (int k = 0; k < 16; k++) {
            float a[8], b[8];
            *(float4*)&a[0] = *(const float4*)&As[cur][k][ty * 4];
            *(float4*)&a[4] = *(const float4*)&As[cur][k][ty * 4 + 64];
            *(float4*)&b[0] = *(const float4*)&Bs[cur][k][tx * 4];
            *(float4*)&b[4] = *(const float4*)&Bs[cur][k][tx * 4 + 64];
#pragma unroll
            for (int i = 0; i < 8; i++)
#pragma unroll
                for (int j = 0; j < 8; j++)
                    acc[i][j] = fmaf(a[i], b[j], acc[i][j]);
        }

        if (more) {
            As[nxt][ak + 0][arow] = av0.x; As[nxt][ak + 1][arow] = av0.y;
            As[nxt][ak + 2][arow] = av0.z; As[nxt][ak + 3][arow] = av0.w;
            As[nxt][ak + 4][arow] = av1.x; As[nxt][ak + 5][arow] = av1.y;
            As[nxt][ak + 6][arow] = av1.z; As[nxt][ak + 7][arow] = av1.w;
            cp_wait0();
        }
        __syncthreads();
    }

#pragma unroll
    for (int ih = 0; ih < 2; ih++) {
#pragma unroll
        for (int i = 0; i < 4; i++) {
            int r = row0 + ih * 64 + ty * 4 + i;
#pragma unroll
            for (int jh = 0; jh < 2; jh++) {
                int c = col0 + jh * 64 + tx * 4;
                float4 v;
                v.x = acc[ih * 4 + i][jh * 4 + 0] + bias[c + 0];
                v.y = acc[ih * 4 + i][jh * 4 + 1] + bias[c + 1];
                v.z = acc[ih * 4 + i][jh * 4 + 2] + bias[c + 2];
                v.w = acc[ih * 4 + i][jh * 4 + 3] + bias[c + 3];
                if (RELU) {
                    v.x = fmaxf(v.x, 0.f); v.y = fmaxf(v.y, 0.f);
                    v.z = fmaxf(v.z, 0.f); v.w = fmaxf(v.w, 0.f);
                }
                *(float4*)&C[(long)r * N + c] = v;
            }
        }
    }
}

// ================= SGEMM 64x64x16, 256 thr, 4x4 micro (N=128 head) ============
__global__ __launch_bounds__(256) void sgemm64(
    const float* __restrict__ A, const float* __restrict__ B,
    const float* __restrict__ bias, float* __restrict__ C,
    int M, int N, int K)
{
    __shared__ float As[16][64];
    __shared__ float Bs[16][64];

    const int tid = threadIdx.x;
    const int tx = tid & 15;
    const int ty = tid >> 4;
    const int row0 = blockIdx.y * 64;
    const int col0 = blockIdx.x * 64;

    const int arow = tid >> 2;          // 0..63
    const int ak   = (tid & 3) << 2;    // 0..12
    const int bk   = tid >> 4;          // 0..15
    const int bcol = (tid & 15) << 2;   // 0..60

    const float* Ap = A + (long)(row0 + arow) * K + ak;
    const float* Bp = B + (long)bk * N + col0 + bcol;

    float acc[4][4];
#pragma unroll
    for (int i = 0; i < 4; i++)
#pragma unroll
        for (int j = 0; j < 4; j++) acc[i][j] = 0.f;

    for (int k0 = 0; k0 < K; k0 += 16) {
        float4 av = *(const float4*)(Ap + k0);
        float4 bv = *(const float4*)(Bp + (long)k0 * N);
        As[ak + 0][arow] = av.x;
        As[ak + 1][arow] = av.y;
        As[ak + 2][arow] = av.z;
        As[ak + 3][arow] = av.w;
        *(float4*)&Bs[bk][bcol] = bv;
        __syncthreads();
#pragma unroll
        for (int k = 0; k < 16; k++) {
            float a[4], b[4];
            *(float4*)&a[0] = *(const float4*)&As[k][ty * 4];
            *(float4*)&b[0] = *(const float4*)&Bs[k][tx * 4];
#pragma unroll
            for (int i = 0; i < 4; i++)
#pragma unroll
                for (int j = 0; j < 4; j++)
                    acc[i][j] = fmaf(a[i], b[j], acc[i][j]);
        }
        __syncthreads();
    }

#pragma unroll
    for (int i = 0; i < 4; i++) {
        int r = row0 + ty * 4 + i;
        int c = col0 + tx * 4;
        float4 v;
        v.x = acc[i][0] + bias[c + 0];
        v.y = acc[i][1] + bias[c + 1];
        v.z = acc[i][2] + bias[c + 2];
        v.w = acc[i][3] + bias[c + 3];
        *(float4*)&C[(long)r * N + c] = v;
    }
}

// ================= row L2-normalize (one warp per 128-float row) ==============
__global__ __launch_bounds__(256) void normalize_kernel(float* __restrict__ f)
{
    int row  = blockIdx.x * 8 + (threadIdx.x >> 5);
    int lane = threadIdx.x & 31;
    float4 v = ((const float4*)f)[row * 32 + lane];
    float s = v.x * v.x + v.y * v.y + v.z * v.z + v.w * v.w;
#pragma unroll
    for (int o = 16; o; o >>= 1) s += __shfl_xor_sync(0xffffffffu, s, o);
    float r = rsqrtf(s);
    v.x *= r; v.y *= r; v.z *= r; v.w *= r;
    ((float4*)f)[row * 32 + lane] = v;
}

// ================= positive-pair similarity + zero S ==========================
__global__ __launch_bounds__(256) void pos_kernel(
    const float* __restrict__ f, float* __restrict__ pos, float* __restrict__ S)
{
    int row  = blockIdx.x * 8 + (threadIdx.x >> 5);
    int lane = threadIdx.x & 31;
    int partner = (row + 4096) & 8191;
    float4 a = ((const float4*)f)[row * 32 + lane];
    float4 b = ((const float4*)f)[partner * 32 + lane];
    float s = a.x * b.x + a.y * b.y + a.z * b.z + a.w * b.w;
#pragma unroll
    for (int o = 16; o; o >>= 1) s += __shfl_xor_sync(0xffffffffu, s, o);
    if (lane == 0) { pos[row] = s * TINV; S[row] = 0.f; }
}

// ================= fused sim + sum-of-exp =====================================
// grid = (2 column halves, 128 row tiles of 64). Block: 128 thr, 8x8 micro.
// Conflict-free fragments: a = {rowsT[k][ty*4], rowsT[k][ty*4+32]},
//                          b = {colsT[k][tx*4], colsT[k][tx*4+64]}.
// Thread rows: {ty*4+i, 32+ty*4+i}; cols: {tx*4+j, 64+tx*4+j}.
__global__ __launch_bounds__(128) void loss_kernel(
    const float* __restrict__ f, float* __restrict__ S)
{
    extern __shared__ float sm[];
    float* rowsT = sm;            // [k][row]  128*64
    float* colsT = sm + 128 * 64; // [k][col]  128*128

    const int tid = threadIdx.x;
    const int tx = tid & 15;
    const int ty = tid >> 4;      // 0..7
    const int r0 = blockIdx.y * 64;
    const int cbase = blockIdx.x * 4096;

    // load 64 rows, transposed to k-major
    for (int q = tid; q < 64 * 32; q += 128) {
        int r  = q & 63;
        int k4 = q >> 6;
        float4 v = ((const float4*)f)[(r0 + r) * 32 + k4];
        rowsT[(k4 * 4 + 0) * 64 + r] = v.x;
        rowsT[(k4 * 4 + 1) * 64 + r] = v.y;
        rowsT[(k4 * 4 + 2) * 64 + r] = v.z;
        rowsT[(k4 * 4 + 3) * 64 + r] = v.w;
    }

    float accS[8];
#pragma unroll
    for (int i = 0; i < 8; i++) accS[i] = 0.f;

    for (int ct = 0; ct < 32; ct++) {
        int c0 = cbase + ct * 128;
        __syncthreads();
        for (int q = tid; q < 128 * 32; q += 128) {
            int c  = q & 127;
            int k4 = q >> 7;
            float4 v = ((const float4*)f)[(c0 + c) * 32 + k4];
            colsT[(k4 * 4 + 0) * 128 + c] = v.x;
            colsT[(k4 * 4 + 1) * 128 + c] = v.y;
            colsT[(k4 * 4 + 2) * 128 + c] = v.z;
            colsT[(k4 * 4 + 3) * 128 + c] = v.w;
        }
        __syncthreads();

        float dotv[8][8];
#pragma unroll
        for (int i = 0; i < 8; i++)
#pragma unroll
            for (int j = 0; j < 8; j++) dotv[i][j] = 0.f;

#pragma unroll 4
        for (int k = 0; k < 128; k++) {
            float a[8], b[8];
            *(float4*)&a[0] = *(const float4*)&rowsT[k * 64 + ty * 4];
            *(float4*)&a[4] = *(const float4*)&rowsT[k * 64 + ty * 4 + 32];
            *(float4*)&b[0] = *(const float4*)&colsT[k * 128 + tx * 4];
            *(float4*)&b[4] = *(const float4*)&colsT[k * 128 + tx * 4 + 64];
#pragma unroll
            for (int i = 0; i < 8; i++)
#pragma unroll
                for (int j = 0; j < 8; j++)
                    dotv[i][j] = fmaf(a[i], b[j], dotv[i][j]);
        }

#pragma unroll
        for (int ih = 0; ih < 2; ih++) {
#pragma unroll
            for (int i = 0; i < 4; i++) {
                int gi = r0 + ih * 32 + ty * 4 + i;
#pragma unroll
                for (int jh = 0; jh < 2; jh++) {
#pragma unroll
                    for (int j = 0; j < 4; j++) {
                        int gj = c0 + jh * 64 + tx * 4 + j;
                        float e = __expf(dotv[ih * 4 + i][jh * 4 + j] * TINV - TINV);
                        accS[ih * 4 + i] += (gi != gj) ? e : 0.f;
                    }
                }
            }
        }
    }

    // per-row cross-thread reduction (16 tx lanes per row) via smem reuse
    __syncthreads();
#pragma unroll
    for (int ih = 0; ih < 2; ih++)
#pragma unroll
        for (int i = 0; i < 4; i++) {
            int rloc = ih * 32 + ty * 4 + i;
            colsT[rloc * 16 + tx] = accS[ih * 4 + i];
        }
    __syncthreads();
    if (tid < 64) {
        float s = 0.f;
#pragma unroll
        for (int t = 0; t < 16; t++) s += colsT[tid * 16 + t];
        atomicAdd(&S[r0 + tid], s);
    }
}

// ================= final deterministic reduction ==============================
__global__ __launch_bounds__(256) void final_kernel(
    const float* __restrict__ S, const float* __restrict__ pos,
    float* __restrict__ out)
{
    __shared__ float sm[256];
    float v = 0.f;
    for (int i = threadIdx.x; i < 8192; i += 256)
        v += TINV + logf(S[i]) - pos[i];
    sm[threadIdx.x] = v;
    __syncthreads();
    for (int o = 128; o; o >>= 1) {
        if (threadIdx.x < o) sm[threadIdx.x] += sm[threadIdx.x + o];
        __syncthreads();
    }
    if (threadIdx.x == 0) out[0] = sm[0] * (1.0f / 8192.0f);
}

// ================= launch =====================================================
extern "C" void kernel_launch(void* const* d_in, const int* in_sizes, int n_in,
                              void* d_out, int out_size)
{
    const float* x[2] = {(const float*)d_in[0], (const float*)d_in[1]};
    const float* W0 = (const float*)d_in[2];
    const float* b0 = (const float*)d_in[3];
    const float* W1 = (const float*)d_in[4];
    const float* b1 = (const float*)d_in[5];
    const float* W2 = (const float*)d_in[6];
    const float* b2 = (const float*)d_in[7];
    float* out = (float*)d_out;

    float *act0, *act1, *feat, *pos, *S;
    cudaGetSymbolAddress((void**)&act0, g_act0);
    cudaGetSymbolAddress((void**)&act1, g_act1);
    cudaGetSymbolAddress((void**)&feat, g_feat);
    cudaGetSymbolAddress((void**)&pos, g_pos);
    cudaGetSymbolAddress((void**)&S, g_S);

    cudaFuncSetAttribute(loss_kernel,
                         cudaFuncAttributeMaxDynamicSharedMemorySize, 98304);

    dim3 gBig(2048 / 128, 4096 / 128);   // (16, 32)
    dim3 gSmall(128 / 64, 4096 / 64);    // (2, 64)

    for (int v = 0; v < 2; v++) {
        sgemm128<true ><<<gBig, 256>>>(x[v], W0, b0, act0, 4096, 2048, 2048);
        sgemm128<false><<<gBig, 256>>>(act0, W1, b1, act1, 4096, 2048, 2048);
        sgemm64<<<gSmall, 256>>>(act1, W2, b2, feat + (long)v * 4096 * 128,
                                 4096, 128, 2048);
    }
    normalize_kernel<<<1024, 256>>>(feat);
    pos_kernel<<<1024, 256>>>(feat, pos, S);
    loss_kernel<<<dim3(2, 128), 128, 98304>>>(feat, S);
    final_kernel<<<1, 256>>>(S, pos, out);
}

// round 5
// speedup vs baseline: 1.9518x; 1.6806x over previous
#include <cuda_runtime.h>
#include <cuda_bf16.h>
#include <stdint.h>
#include <math.h>

#define TINV 14.2857142857142857f  /* 1 / 0.07 */

// -------- scratch (no allocations allowed) --------
static __device__ __nv_bfloat16 g_xhi[4096 * 2048];   // 16 MB
static __device__ __nv_bfloat16 g_xlo[4096 * 2048];   // 16 MB
static __device__ __nv_bfloat16 g_w0h[2048 * 2048];   // 8 MB (transposed W0)
static __device__ __nv_bfloat16 g_w0l[2048 * 2048];
static __device__ __nv_bfloat16 g_w1h[2048 * 2048];   // 8 MB (transposed W1)
static __device__ __nv_bfloat16 g_w1l[2048 * 2048];
static __device__ __nv_bfloat16 g_a0h[4096 * 2048];   // 16 MB
static __device__ __nv_bfloat16 g_a0l[4096 * 2048];
static __device__ float g_act1[4096 * 2048];           // 32 MB
static __device__ float g_feat[8192 * 128];            // 4 MB
static __device__ float g_pos[8192];
static __device__ float g_S[8192];

// ======================= PTX helpers (baseline ISA only) =====================
__device__ __forceinline__ void cp_async16(unsigned int saddr, const void* gptr) {
    asm volatile("cp.async.ca.shared.global [%0], [%1], 16;" :: "r"(saddr), "l"(gptr));
}
__device__ __forceinline__ void cp_commit() {
    asm volatile("cp.async.commit_group;");
}
__device__ __forceinline__ unsigned int smem_u32(const void* p) {
    unsigned int a;
    asm("{ .reg .u64 t; cvta.to.shared.u64 t, %1; cvt.u32.u64 %0, t; }" : "=r"(a) : "l"(p));
    return a;
}
__device__ __forceinline__ void ldmat4(unsigned int* r, unsigned int addr) {
    asm volatile("ldmatrix.sync.aligned.m8n8.x4.shared.b16 {%0,%1,%2,%3}, [%4];"
        : "=r"(r[0]), "=r"(r[1]), "=r"(r[2]), "=r"(r[3]) : "r"(addr));
}
__device__ __forceinline__ void mma16816(float* d, const unsigned int* a,
                                         unsigned int b0, unsigned int b1) {
    asm volatile(
        "mma.sync.aligned.m16n8k16.row.col.f32.bf16.bf16.f32 "
        "{%0,%1,%2,%3}, {%4,%5,%6,%7}, {%8,%9}, {%0,%1,%2,%3};"
        : "+f"(d[0]), "+f"(d[1]), "+f"(d[2]), "+f"(d[3])
        : "r"(a[0]), "r"(a[1]), "r"(a[2]), "r"(a[3]), "r"(b0), "r"(b1));
}

// ======================= bf16-split warp-MMA GEMM ============================
// C[4096 x 2048] = A[4096 x 2048] @ W^T + bias.  A, W given as bf16 hi/lo pairs,
// W pre-transposed to [N, K] K-major (mma .col operand).
// CTA tile 128x128, 8 warps as 4(m) x 2(n), warp tile 32x64, k-chunk 32,
// 3-stage cp.async pipeline. Smem rows padded to 80B for conflict-free ldmatrix.
#define ROWB 80                     /* bytes per smem row: 64 data + 16 pad */
#define OFF_AH 0
#define OFF_AL (128 * ROWB)
#define OFF_BH (2 * 128 * ROWB)
#define OFF_BL (3 * 128 * ROWB)
#define STAGE  (4 * 128 * ROWB)     /* 40960 B */
#define SMEM_BIAS 0                 /* 128 floats */
#define SMEM_STAGE0 1024
#define GEMM_SMEM (SMEM_STAGE0 + 3 * STAGE)   /* 123904 B */

template <bool RELU, bool OUT_PAIR>
__global__ __launch_bounds__(256) void gemm_mma(
    const __nv_bfloat16* __restrict__ Ahi, const __nv_bfloat16* __restrict__ Alo,
    const __nv_bfloat16* __restrict__ Bhi, const __nv_bfloat16* __restrict__ Blo,
    const float* __restrict__ bias,
    __nv_bfloat16* __restrict__ Chi, __nv_bfloat16* __restrict__ Clo,
    float* __restrict__ Cf)
{
    extern __shared__ char smem[];
    const unsigned int sb = smem_u32(smem);
    const int tid  = threadIdx.x;
    const int lane = tid & 31;
    const int wid  = tid >> 5;
    const int wm   = wid >> 1;          // 0..3  (m)
    const int wn   = wid & 1;           // 0..1  (n)
    const int row0 = blockIdx.x * 128;
    const int col0 = blockIdx.y * 128;
    const int K = 2048;
    const int NKT = 64;                 // K / 32

    if (tid < 128) ((float*)(smem + SMEM_BIAS))[tid] = bias[col0 + tid];

    // ---- staging mapping: thread t -> row t>>1, 32B half t&1 of each array ----
    const int srow = tid >> 1;
    const int shal = tid & 1;
    const __nv_bfloat16* gAh = Ahi + (long)(row0 + srow) * K + shal * 16;
    const __nv_bfloat16* gAl = Alo + (long)(row0 + srow) * K + shal * 16;
    const __nv_bfloat16* gBh = Bhi + (long)(col0 + srow) * K + shal * 16;
    const __nv_bfloat16* gBl = Blo + (long)(col0 + srow) * K + shal * 16;
    const unsigned int sro = srow * ROWB + shal * 32;

#define LOAD_STAGE(stg, k0) do { \
        cp_async16((stg) + OFF_AH + sro,      gAh + (k0)); \
        cp_async16((stg) + OFF_AH + sro + 16, gAh + (k0) + 8); \
        cp_async16((stg) + OFF_AL + sro,      gAl + (k0)); \
        cp_async16((stg) + OFF_AL + sro + 16, gAl + (k0) + 8); \
        cp_async16((stg) + OFF_BH + sro,      gBh + (k0)); \
        cp_async16((stg) + OFF_BH + sro + 16, gBh + (k0) + 8); \
        cp_async16((stg) + OFF_BL + sro,      gBl + (k0)); \
        cp_async16((stg) + OFF_BL + sro + 16, gBl + (k0) + 8); \
    } while (0)

    // prologue: stages 0..2
#pragma unroll
    for (int b = 0; b < 3; b++) {
        LOAD_STAGE(sb + SMEM_STAGE0 + b * STAGE, b * 32);
        cp_commit();
    }

    float acc[2][8][4];
#pragma unroll
    for (int i = 0; i < 2; i++)
#pragma unroll
        for (int j = 0; j < 8; j++)
#pragma unroll
            for (int q = 0; q < 4; q++) acc[i][j][q] = 0.f;

    // ldmatrix lane addressing (within a 16x16 A atom / 16-row B pair)
    const unsigned int a_row  = lane & 15;              // row within atom
    const unsigned int a_koff = (lane >> 4) * 16;       // 0 or 16 bytes (k half)
    const unsigned int b_row  = (lane & 7) + ((lane >> 4) & 1) * 8;
    const unsigned int b_koff = ((lane >> 3) & 1) * 16;

    for (int kt = 0; kt < NKT; kt++) {
        const unsigned int stg = sb + SMEM_STAGE0 + (kt % 3) * STAGE;
        asm volatile("cp.async.wait_group 2;" ::: "memory");
        __syncthreads();

#pragma unroll
        for (int s = 0; s < 2; s++) {       // two k16 steps per chunk
            const unsigned int kb = s * 32; // byte offset in 64B row data

            unsigned int ah[2][4], al[2][4];
#pragma unroll
            for (int ma = 0; ma < 2; ma++) {
                unsigned int roff = (wm * 32 + ma * 16 + a_row) * ROWB + kb + a_koff;
                ldmat4(ah[ma], stg + OFF_AH + roff);
                ldmat4(al[ma], stg + OFF_AL + roff);
            }
            unsigned int bh[4][4], bl[4][4];
#pragma unroll
            for (int nb = 0; nb < 4; nb++) {
                unsigned int roff = (wn * 64 + nb * 16 + b_row) * ROWB + kb + b_koff;
                ldmat4(bh[nb], stg + OFF_BH + roff);
                ldmat4(bl[nb], stg + OFF_BL + roff);
            }
#pragma unroll
            for (int ma = 0; ma < 2; ma++)
#pragma unroll
                for (int na = 0; na < 8; na++) {
                    unsigned int h0 = bh[na >> 1][(na & 1) * 2];
                    unsigned int h1 = bh[na >> 1][(na & 1) * 2 + 1];
                    unsigned int l0 = bl[na >> 1][(na & 1) * 2];
                    unsigned int l1 = bl[na >> 1][(na & 1) * 2 + 1];
                    mma16816(acc[ma][na], ah[ma], h0, h1);
                    mma16816(acc[ma][na], ah[ma], l0, l1);
                    mma16816(acc[ma][na], al[ma], h0, h1);
                }
        }

        __syncthreads();
        if (kt + 3 < NKT) LOAD_STAGE(stg, (kt + 3) * 32);
        cp_commit();   // always commit (possibly empty) to keep group count aligned
    }

    // ---- epilogue ----
    const float* bs = (const float*)(smem + SMEM_BIAS);
    const int ccol = wn * 64;            // warp col base within tile
#pragma unroll
    for (int ma = 0; ma < 2; ma++) {
#pragma unroll
        for (int na = 0; na < 8; na++) {
            int c  = ccol + na * 8 + (lane & 3) * 2;
            int r1 = row0 + wm * 32 + ma * 16 + (lane >> 2);
            int r2 = r1 + 8;
            float v0 = acc[ma][na][0] + bs[c];
            float v1 = acc[ma][na][1] + bs[c + 1];
            float v2 = acc[ma][na][2] + bs[c];
            float v3 = acc[ma][na][3] + bs[c + 1];
            if (RELU) {
                v0 = fmaxf(v0, 0.f); v1 = fmaxf(v1, 0.f);
                v2 = fmaxf(v2, 0.f); v3 = fmaxf(v3, 0.f);
            }
            long o1 = (long)r1 * 2048 + col0 + c;
            long o2 = (long)r2 * 2048 + col0 + c;
            if (OUT_PAIR) {
                __nv_bfloat16 h0 = __float2bfloat16(v0);
                __nv_bfloat16 h1 = __float2bfloat16(v1);
                __nv_bfloat16 h2 = __float2bfloat16(v2);
                __nv_bfloat16 h3 = __float2bfloat16(v3);
                __nv_bfloat162 hp1 = {h0, h1}, hp2 = {h2, h3};
                __nv_bfloat162 lp1 = {__float2bfloat16(v0 - __bfloat162float(h0)),
                                      __float2bfloat16(v1 - __bfloat162float(h1))};
                __nv_bfloat162 lp2 = {__float2bfloat16(v2 - __bfloat162float(h2)),
                                      __float2bfloat16(v3 - __bfloat162float(h3))};
                *(__nv_bfloat162*)&Chi[o1] = hp1;
                *(__nv_bfloat162*)&Chi[o2] = hp2;
                *(__nv_bfloat162*)&Clo[o1] = lp1;
                *(__nv_bfloat162*)&Clo[o2] = lp2;
            } else {
                *(float2*)&Cf[o1] = make_float2(v0, v1);
                *(float2*)&Cf[o2] = make_float2(v2, v3);
            }
        }
    }
#undef LOAD_STAGE
}

// ======================= fp32 -> bf16 hi/lo split (elementwise) ==============
__global__ __launch_bounds__(256) void split_kernel(
    const float4* __restrict__ in, uint2* __restrict__ hi, uint2* __restrict__ lo)
{
    int i = blockIdx.x * 256 + threadIdx.x;
    float4 v = in[i];
    __nv_bfloat16 h[4], l[4];
    float vv[4] = {v.x, v.y, v.z, v.w};
#pragma unroll
    for (int j = 0; j < 4; j++) {
        h[j] = __float2bfloat16(vv[j]);
        l[j] = __float2bfloat16(vv[j] - __bfloat162float(h[j]));
    }
    hi[i] = *(uint2*)h;
    lo[i] = *(uint2*)l;
}

// ============== W [K,N] -> W^T hi/lo bf16 [N,K] (transpose + split) ==========
__global__ __launch_bounds__(256) void tsplit_kernel(
    const float* __restrict__ W, __nv_bfloat16* __restrict__ Th,
    __nv_bfloat16* __restrict__ Tl)
{
    __shared__ float t[32][33];
    const int n = 2048;
    int x = blockIdx.x * 32 + threadIdx.x % 32;
    int y0 = blockIdx.y * 32;
    int ty = threadIdx.x / 32;  // 0..7
#pragma unroll
    for (int i = 0; i < 4; i++)
        t[ty + 8 * i][threadIdx.x % 32] = W[(long)(y0 + ty + 8 * i) * n + x];
    __syncthreads();
    int xo = blockIdx.y * 32 + threadIdx.x % 32;
    int yo = blockIdx.x * 32;
#pragma unroll
    for (int i = 0; i < 4; i++) {
        float v = t[threadIdx.x % 32][ty + 8 * i];
        __nv_bfloat16 h = __float2bfloat16(v);
        __nv_bfloat16 l = __float2bfloat16(v - __bfloat162float(h));
        Th[(long)(yo + ty + 8 * i) * n + xo] = h;
        Tl[(long)(yo + ty + 8 * i) * n + xo] = l;
    }
}

// ================= SGEMM 64x64x16 (head, N=128) — scalar ======================
__global__ __launch_bounds__(256) void sgemm64(
    const float* __restrict__ A, const float* __restrict__ B,
    const float* __restrict__ bias, float* __restrict__ C,
    int M, int N, int K)
{
    __shared__ float As[16][64];
    __shared__ float Bs[16][64];

    const int tid = threadIdx.x;
    const int tx = tid & 15;
    const int ty = tid >> 4;
    const int row0 = blockIdx.y * 64;
    const int col0 = blockIdx.x * 64;

    const int arow = tid >> 2;
    const int ak   = (tid & 3) << 2;
    const int bk   = tid >> 4;
    const int bcol = (tid & 15) << 2;

    const float* Ap = A + (long)(row0 + arow) * K + ak;
    const float* Bp = B + (long)bk * N + col0 + bcol;

    float acc[4][4];
#pragma unroll
    for (int i = 0; i < 4; i++)
#pragma unroll
        for (int j = 0; j < 4; j++) acc[i][j] = 0.f;

    for (int k0 = 0; k0 < K; k0 += 16) {
        float4 av = *(const float4*)(Ap + k0);
        float4 bv = *(const float4*)(Bp + (long)k0 * N);
        As[ak + 0][arow] = av.x;
        As[ak + 1][arow] = av.y;
        As[ak + 2][arow] = av.z;
        As[ak + 3][arow] = av.w;
        *(float4*)&Bs[bk][bcol] = bv;
        __syncthreads();
#pragma unroll
        for (int k = 0; k < 16; k++) {
            float a[4], b[4];
            *(float4*)&a[0] = *(const float4*)&As[k][ty * 4];
            *(float4*)&b[0] = *(const float4*)&Bs[k][tx * 4];
#pragma unroll
            for (int i = 0; i < 4; i++)
#pragma unroll
                for (int j = 0; j < 4; j++)
                    acc[i][j] = fmaf(a[i], b[j], acc[i][j]);
        }
        __syncthreads();
    }

#pragma unroll
    for (int i = 0; i < 4; i++) {
        int r = row0 + ty * 4 + i;
        int c = col0 + tx * 4;
        float4 v;
        v.x = acc[i][0] + bias[c + 0];
        v.y = acc[i][1] + bias[c + 1];
        v.z = acc[i][2] + bias[c + 2];
        v.w = acc[i][3] + bias[c + 3];
        *(float4*)&C[(long)r * N + c] = v;
    }
}

// ================= row L2-normalize ==========================================
__global__ __launch_bounds__(256) void normalize_kernel(float* __restrict__ f)
{
    int row  = blockIdx.x * 8 + (threadIdx.x >> 5);
    int lane = threadIdx.x & 31;
    float4 v = ((const float4*)f)[row * 32 + lane];
    float s = v.x * v.x + v.y * v.y + v.z * v.z + v.w * v.w;
#pragma unroll
    for (int o = 16; o; o >>= 1) s += __shfl_xor_sync(0xffffffffu, s, o);
    float r = rsqrtf(s);
    v.x *= r; v.y *= r; v.z *= r; v.w *= r;
    ((float4*)f)[row * 32 + lane] = v;
}

// ================= positive-pair similarity + zero S ==========================
__global__ __launch_bounds__(256) void pos_kernel(
    const float* __restrict__ f, float* __restrict__ pos, float* __restrict__ S)
{
    int row  = blockIdx.x * 8 + (threadIdx.x >> 5);
    int lane = threadIdx.x & 31;
    int partner = (row + 4096) & 8191;
    float4 a = ((const float4*)f)[row * 32 + lane];
    float4 b = ((const float4*)f)[partner * 32 + lane];
    float s = a.x * b.x + a.y * b.y + a.z * b.z + a.w * b.w;
#pragma unroll
    for (int o = 16; o; o >>= 1) s += __shfl_xor_sync(0xffffffffu, s, o);
    if (lane == 0) { pos[row] = s * TINV; S[row] = 0.f; }
}

// ================= fused sim + sum-of-exp =====================================
__global__ __launch_bounds__(128) void loss_kernel(
    const float* __restrict__ f, float* __restrict__ S)
{
    extern __shared__ float sm[];
    float* rowsT = sm;            // [k][row]  128*64
    float* colsT = sm + 128 * 64; // [k][col]  128*128

    const int tid = threadIdx.x;
    const int tx = tid & 15;
    const int ty = tid >> 4;
    const int r0 = blockIdx.y * 64;
    const int cbase = blockIdx.x * 4096;

    for (int q = tid; q < 64 * 32; q += 128) {
        int r  = q & 63;
        int k4 = q >> 6;
        float4 v = ((const float4*)f)[(r0 + r) * 32 + k4];
        rowsT[(k4 * 4 + 0) * 64 + r] = v.x;
        rowsT[(k4 * 4 + 1) * 64 + r] = v.y;
        rowsT[(k4 * 4 + 2) * 64 + r] = v.z;
        rowsT[(k4 * 4 + 3) * 64 + r] = v.w;
    }

    float accS[8];
#pragma unroll
    for (int i = 0; i < 8; i++) accS[i] = 0.f;

    for (int ct = 0; ct < 32; ct++) {
        int c0 = cbase + ct * 128;
        __syncthreads();
        for (int q = tid; q < 128 * 32; q += 128) {
            int c  = q & 127;
            int k4 = q >> 7;
            float4 v = ((const float4*)f)[(c0 + c) * 32 + k4];
            colsT[(k4 * 4 + 0) * 128 + c] = v.x;
            colsT[(k4 * 4 + 1) * 128 + c] = v.y;
            colsT[(k4 * 4 + 2) * 128 + c] = v.z;
            colsT[(k4 * 4 + 3) * 128 + c] = v.w;
        }
        __syncthreads();

        float dotv[8][8];
#pragma unroll
        for (int i = 0; i < 8; i++)
#pragma unroll
            for (int j = 0; j < 8; j++) dotv[i][j] = 0.f;

#pragma unroll 4
        for (int k = 0; k < 128; k++) {
            float a[8], b[8];
            *(float4*)&a[0] = *(const float4*)&rowsT[k * 64 + ty * 4];
            *(float4*)&a[4] = *(const float4*)&rowsT[k * 64 + ty * 4 + 32];
            *(float4*)&b[0] = *(const float4*)&colsT[k * 128 + tx * 4];
            *(float4*)&b[4] = *(const float4*)&colsT[k * 128 + tx * 4 + 64];
#pragma unroll
            for (int i = 0; i < 8; i++)
#pragma unroll
                for (int j = 0; j < 8; j++)
                    dotv[i][j] = fmaf(a[i], b[j], dotv[i][j]);
        }

#pragma unroll
        for (int ih = 0; ih < 2; ih++) {
#pragma unroll
            for (int i = 0; i < 4; i++) {
                int gi = r0 + ih * 32 + ty * 4 + i;
#pragma unroll
                for (int jh = 0; jh < 2; jh++) {
#pragma unroll
                    for (int j = 0; j < 4; j++) {
                        int gj = c0 + jh * 64 + tx * 4 + j;
                        float e = __expf(dotv[ih * 4 + i][jh * 4 + j] * TINV - TINV);
                        accS[ih * 4 + i] += (gi != gj) ? e : 0.f;
                    }
                }
            }
        }
    }

    __syncthreads();
#pragma unroll
    for (int ih = 0; ih < 2; ih++)
#pragma unroll
        for (int i = 0; i < 4; i++) {
            int rloc = ih * 32 + ty * 4 + i;
            colsT[rloc * 16 + tx] = accS[ih * 4 + i];
        }
    __syncthreads();
    if (tid < 64) {
        float s = 0.f;
#pragma unroll
        for (int t = 0; t < 16; t++) s += colsT[tid * 16 + t];
        atomicAdd(&S[r0 + tid], s);
    }
}

// ================= final deterministic reduction ==============================
__global__ __launch_bounds__(256) void final_kernel(
    const float* __restrict__ S, const float* __restrict__ pos,
    float* __restrict__ out)
{
    __shared__ float sm[256];
    float v = 0.f;
    for (int i = threadIdx.x; i < 8192; i += 256)
        v += TINV + logf(S[i]) - pos[i];
    sm[threadIdx.x] = v;
    __syncthreads();
    for (int o = 128; o; o >>= 1) {
        if (threadIdx.x < o) sm[threadIdx.x] += sm[threadIdx.x + o];
        __syncthreads();
    }
    if (threadIdx.x == 0) out[0] = sm[0] * (1.0f / 8192.0f);
}

// ================= launch =====================================================
extern "C" void kernel_launch(void* const* d_in, const int* in_sizes, int n_in,
                              void* d_out, int out_size)
{
    const float* x[2] = {(const float*)d_in[0], (const float*)d_in[1]};
    const float* W0 = (const float*)d_in[2];
    const float* b0 = (const float*)d_in[3];
    const float* W1 = (const float*)d_in[4];
    const float* b1 = (const float*)d_in[5];
    const float* W2 = (const float*)d_in[6];
    const float* b2 = (const float*)d_in[7];
    float* out = (float*)d_out;

    __nv_bfloat16 *xhi, *xlo, *w0h, *w0l, *w1h, *w1l, *a0h, *a0l;
    float *act1, *feat, *pos, *S;
    cudaGetSymbolAddress((void**)&xhi, g_xhi);
    cudaGetSymbolAddress((void**)&xlo, g_xlo);
    cudaGetSymbolAddress((void**)&w0h, g_w0h);
    cudaGetSymbolAddress((void**)&w0l, g_w0l);
    cudaGetSymbolAddress((void**)&w1h, g_w1h);
    cudaGetSymbolAddress((void**)&w1l, g_w1l);
    cudaGetSymbolAddress((void**)&a0h, g_a0h);
    cudaGetSymbolAddress((void**)&a0l, g_a0l);
    cudaGetSymbolAddress((void**)&act1, g_act1);
    cudaGetSymbolAddress((void**)&feat, g_feat);
    cudaGetSymbolAddress((void**)&pos, g_pos);
    cudaGetSymbolAddress((void**)&S, g_S);

    cudaFuncSetAttribute(gemm_mma<true, true>,
                         cudaFuncAttributeMaxDynamicSharedMemorySize, GEMM_SMEM);
    cudaFuncSetAttribute(gemm_mma<false, false>,
                         cudaFuncAttributeMaxDynamicSharedMemorySize, GEMM_SMEM);
    cudaFuncSetAttribute(loss_kernel,
                         cudaFuncAttributeMaxDynamicSharedMemorySize, 98304);

    // weight transpose + split (once per launch)
    dim3 gT(64, 64);
    tsplit_kernel<<<gT, 256>>>(W0, w0h, w0l);
    tsplit_kernel<<<gT, 256>>>(W1, w1h, w1l);

    dim3 gG(32, 16);                      // (m-tiles, n-tiles)
    dim3 gSmall(128 / 64, 4096 / 64);

    for (int v = 0; v < 2; v++) {
        split_kernel<<<(4096 * 2048 / 4) / 256, 256>>>(
            (const float4*)x[v], (uint2*)xhi, (uint2*)xlo);
        gemm_mma<true, true><<<gG, 256, GEMM_SMEM>>>(
            xhi, xlo, w0h, w0l, b0, a0h, a0l, (float*)0);
        gemm_mma<false, false><<<gG, 256, GEMM_SMEM>>>(
            a0h, a0l, w1h, w1l, b1, (__nv_bfloat16*)0, (__nv_bfloat16*)0, act1);
        sgemm64<<<gSmall, 256>>>(act1, W2, b2, feat + (long)v * 4096 * 128,
                                 4096, 128, 2048);
    }
    normalize_kernel<<<1024, 256>>>(feat);
    pos_kernel<<<1024, 256>>>(feat, pos, S);
    loss_kernel<<<dim3(2, 128), 128, 98304>>>(feat, S);
    final_kernel<<<1, 256>>>(S, pos, out);
}

// round 6
// speedup vs baseline: 2.4273x; 1.2436x over previous
#include <cuda_runtime.h>
#include <cuda_bf16.h>
#include <stdint.h>
#include <math.h>

#define TINV 14.2857142857142857f   /* 1 / 0.07 */
#define K1E  20.6099291083577f      /* TINV * log2(e) */

// -------- scratch (no allocations allowed) --------
static __device__ __nv_bfloat16 g_xhi[4096 * 2048];
static __device__ __nv_bfloat16 g_xlo[4096 * 2048];
static __device__ __nv_bfloat16 g_w0h[2048 * 2048];
static __device__ __nv_bfloat16 g_w0l[2048 * 2048];
static __device__ __nv_bfloat16 g_w1h[2048 * 2048];
static __device__ __nv_bfloat16 g_w1l[2048 * 2048];
static __device__ __nv_bfloat16 g_a0h[4096 * 2048];
static __device__ __nv_bfloat16 g_a0l[4096 * 2048];
static __device__ float g_act1[4096 * 2048];
static __device__ float g_feat[8192 * 128];
static __device__ __nv_bfloat16 g_fhi[8192 * 128];
static __device__ __nv_bfloat16 g_flo[8192 * 128];
static __device__ float g_pos[8192];
static __device__ float g_S[8192];

// ======================= PTX helpers (baseline ISA only) =====================
__device__ __forceinline__ void cp_async16(unsigned int saddr, const void* gptr) {
    asm volatile("cp.async.ca.shared.global [%0], [%1], 16;" :: "r"(saddr), "l"(gptr));
}
__device__ __forceinline__ void cp_commit() {
    asm volatile("cp.async.commit_group;");
}
__device__ __forceinline__ unsigned int smem_u32(const void* p) {
    unsigned int a;
    asm("{ .reg .u64 t; cvta.to.shared.u64 t, %1; cvt.u32.u64 %0, t; }" : "=r"(a) : "l"(p));
    return a;
}
__device__ __forceinline__ void ldmat4(unsigned int* r, unsigned int addr) {
    asm volatile("ldmatrix.sync.aligned.m8n8.x4.shared.b16 {%0,%1,%2,%3}, [%4];"
        : "=r"(r[0]), "=r"(r[1]), "=r"(r[2]), "=r"(r[3]) : "r"(addr));
}
__device__ __forceinline__ void mma16816(float* d, const unsigned int* a,
                                         unsigned int b0, unsigned int b1) {
    asm volatile(
        "mma.sync.aligned.m16n8k16.row.col.f32.bf16.bf16.f32 "
        "{%0,%1,%2,%3}, {%4,%5,%6,%7}, {%8,%9}, {%0,%1,%2,%3};"
        : "+f"(d[0]), "+f"(d[1]), "+f"(d[2]), "+f"(d[3])
        : "r"(a[0]), "r"(a[1]), "r"(a[2]), "r"(a[3]), "r"(b0), "r"(b1));
}

// ======================= bf16-split warp-MMA GEMM ============================
// CTA tile 128x128, 8 warps 4(m)x2(n), warp tile 32x64, k-chunk 32,
// 2-stage cp.async pipeline (83 KB smem -> 2 CTAs/SM).
#define ROWB 80
#define OFF_AH 0
#define OFF_AL (128 * ROWB)
#define OFF_BH (2 * 128 * ROWB)
#define OFF_BL (3 * 128 * ROWB)
#define STAGE  (4 * 128 * ROWB)     /* 40960 B */
#define SMEM_BIAS 0
#define SMEM_STAGE0 1024
#define GEMM_SMEM (SMEM_STAGE0 + 2 * STAGE)   /* 82944 B */

template <bool RELU, bool OUT_PAIR>
__global__ __launch_bounds__(256, 2) void gemm_mma(
    const __nv_bfloat16* __restrict__ Ahi, const __nv_bfloat16* __restrict__ Alo,
    const __nv_bfloat16* __restrict__ Bhi, const __nv_bfloat16* __restrict__ Blo,
    const float* __restrict__ bias,
    __nv_bfloat16* __restrict__ Chi, __nv_bfloat16* __restrict__ Clo,
    float* __restrict__ Cf)
{
    extern __shared__ char smem[];
    const unsigned int sb = smem_u32(smem);
    const int tid  = threadIdx.x;
    const int lane = tid & 31;
    const int wid  = tid >> 5;
    const int wm   = wid >> 1;
    const int wn   = wid & 1;
    const int row0 = blockIdx.x * 128;
    const int col0 = blockIdx.y * 128;
    const int K = 2048;
    const int NKT = 64;

    if (tid < 128) ((float*)(smem + SMEM_BIAS))[tid] = bias[col0 + tid];

    const int srow = tid >> 1;
    const int shal = tid & 1;
    const __nv_bfloat16* gAh = Ahi + (long)(row0 + srow) * K + shal * 16;
    const __nv_bfloat16* gAl = Alo + (long)(row0 + srow) * K + shal * 16;
    const __nv_bfloat16* gBh = Bhi + (long)(col0 + srow) * K + shal * 16;
    const __nv_bfloat16* gBl = Blo + (long)(col0 + srow) * K + shal * 16;
    const unsigned int sro = srow * ROWB + shal * 32;

#define LOAD_STAGE(stg, k0) do { \
        cp_async16((stg) + OFF_AH + sro,      gAh + (k0)); \
        cp_async16((stg) + OFF_AH + sro + 16, gAh + (k0) + 8); \
        cp_async16((stg) + OFF_AL + sro,      gAl + (k0)); \
        cp_async16((stg) + OFF_AL + sro + 16, gAl + (k0) + 8); \
        cp_async16((stg) + OFF_BH + sro,      gBh + (k0)); \
        cp_async16((stg) + OFF_BH + sro + 16, gBh + (k0) + 8); \
        cp_async16((stg) + OFF_BL + sro,      gBl + (k0)); \
        cp_async16((stg) + OFF_BL + sro + 16, gBl + (k0) + 8); \
    } while (0)

#pragma unroll
    for (int b = 0; b < 2; b++) {
        LOAD_STAGE(sb + SMEM_STAGE0 + b * STAGE, b * 32);
        cp_commit();
    }

    float acc[2][8][4];
#pragma unroll
    for (int i = 0; i < 2; i++)
#pragma unroll
        for (int j = 0; j < 8; j++)
#pragma unroll
            for (int q = 0; q < 4; q++) acc[i][j][q] = 0.f;

    const unsigned int a_row  = lane & 15;
    const unsigned int a_koff = (lane >> 4) * 16;
    const unsigned int b_row  = (lane & 7) + ((lane >> 4) & 1) * 8;
    const unsigned int b_koff = ((lane >> 3) & 1) * 16;

    for (int kt = 0; kt < NKT; kt++) {
        const unsigned int stg = sb + SMEM_STAGE0 + (kt & 1) * STAGE;
        asm volatile("cp.async.wait_group 1;" ::: "memory");
        __syncthreads();

#pragma unroll
        for (int s = 0; s < 2; s++) {
            const unsigned int kb = s * 32;
            unsigned int ah[2][4], al[2][4];
#pragma unroll
            for (int ma = 0; ma < 2; ma++) {
                unsigned int roff = (wm * 32 + ma * 16 + a_row) * ROWB + kb + a_koff;
                ldmat4(ah[ma], stg + OFF_AH + roff);
                ldmat4(al[ma], stg + OFF_AL + roff);
            }
            unsigned int bh[4][4], bl[4][4];
#pragma unroll
            for (int nb = 0; nb < 4; nb++) {
                unsigned int roff = (wn * 64 + nb * 16 + b_row) * ROWB + kb + b_koff;
                ldmat4(bh[nb], stg + OFF_BH + roff);
                ldmat4(bl[nb], stg + OFF_BL + roff);
            }
#pragma unroll
            for (int ma = 0; ma < 2; ma++)
#pragma unroll
                for (int na = 0; na < 8; na++) {
                    unsigned int h0 = bh[na >> 1][(na & 1) * 2];
                    unsigned int h1 = bh[na >> 1][(na & 1) * 2 + 1];
                    unsigned int l0 = bl[na >> 1][(na & 1) * 2];
                    unsigned int l1 = bl[na >> 1][(na & 1) * 2 + 1];
                    mma16816(acc[ma][na], ah[ma], h0, h1);
                    mma16816(acc[ma][na], ah[ma], l0, l1);
                    mma16816(acc[ma][na], al[ma], h0, h1);
                }
        }

        __syncthreads();
        if (kt + 2 < NKT) LOAD_STAGE(stg, (kt + 2) * 32);
        cp_commit();
    }

    const float* bs = (const float*)(smem + SMEM_BIAS);
    const int ccol = wn * 64;
#pragma unroll
    for (int ma = 0; ma < 2; ma++) {
#pragma unroll
        for (int na = 0; na < 8; na++) {
            int c  = ccol + na * 8 + (lane & 3) * 2;
            int r1 = row0 + wm * 32 + ma * 16 + (lane >> 2);
            int r2 = r1 + 8;
            float v0 = acc[ma][na][0] + bs[c];
            float v1 = acc[ma][na][1] + bs[c + 1];
            float v2 = acc[ma][na][2] + bs[c];
            float v3 = acc[ma][na][3] + bs[c + 1];
            if (RELU) {
                v0 = fmaxf(v0, 0.f); v1 = fmaxf(v1, 0.f);
                v2 = fmaxf(v2, 0.f); v3 = fmaxf(v3, 0.f);
            }
            long o1 = (long)r1 * 2048 + col0 + c;
            long o2 = (long)r2 * 2048 + col0 + c;
            if (OUT_PAIR) {
                __nv_bfloat16 h0 = __float2bfloat16(v0);
                __nv_bfloat16 h1 = __float2bfloat16(v1);
                __nv_bfloat16 h2 = __float2bfloat16(v2);
                __nv_bfloat16 h3 = __float2bfloat16(v3);
                __nv_bfloat162 hp1 = {h0, h1}, hp2 = {h2, h3};
                __nv_bfloat162 lp1 = {__float2bfloat16(v0 - __bfloat162float(h0)),
                                      __float2bfloat16(v1 - __bfloat162float(h1))};
                __nv_bfloat162 lp2 = {__float2bfloat16(v2 - __bfloat162float(h2)),
                                      __float2bfloat16(v3 - __bfloat162float(h3))};
                *(__nv_bfloat162*)&Chi[o1] = hp1;
                *(__nv_bfloat162*)&Chi[o2] = hp2;
                *(__nv_bfloat162*)&Clo[o1] = lp1;
                *(__nv_bfloat162*)&Clo[o2] = lp2;
            } else {
                *(float2*)&Cf[o1] = make_float2(v0, v1);
                *(float2*)&Cf[o2] = make_float2(v2, v3);
            }
        }
    }
#undef LOAD_STAGE
}

// ======================= fp32 -> bf16 hi/lo split =============================
__global__ __launch_bounds__(256) void split_kernel(
    const float4* __restrict__ in, uint2* __restrict__ hi, uint2* __restrict__ lo)
{
    int i = blockIdx.x * 256 + threadIdx.x;
    float4 v = in[i];
    __nv_bfloat16 h[4], l[4];
    float vv[4] = {v.x, v.y, v.z, v.w};
#pragma unroll
    for (int j = 0; j < 4; j++) {
        h[j] = __float2bfloat16(vv[j]);
        l[j] = __float2bfloat16(vv[j] - __bfloat162float(h[j]));
    }
    hi[i] = *(uint2*)h;
    lo[i] = *(uint2*)l;
}

// ============== W [K,N] -> W^T hi/lo bf16 [N,K] ===============================
__global__ __launch_bounds__(256) void tsplit_kernel(
    const float* __restrict__ W, __nv_bfloat16* __restrict__ Th,
    __nv_bfloat16* __restrict__ Tl)
{
    __shared__ float t[32][33];
    const int n = 2048;
    int x = blockIdx.x * 32 + threadIdx.x % 32;
    int y0 = blockIdx.y * 32;
    int ty = threadIdx.x / 32;
#pragma unroll
    for (int i = 0; i < 4; i++)
        t[ty + 8 * i][threadIdx.x % 32] = W[(long)(y0 + ty + 8 * i) * n + x];
    __syncthreads();
    int xo = blockIdx.y * 32 + threadIdx.x % 32;
    int yo = blockIdx.x * 32;
#pragma unroll
    for (int i = 0; i < 4; i++) {
        float v = t[threadIdx.x % 32][ty + 8 * i];
        __nv_bfloat16 h = __float2bfloat16(v);
        __nv_bfloat16 l = __float2bfloat16(v - __bfloat162float(h));
        Th[(long)(yo + ty + 8 * i) * n + xo] = h;
        Tl[(long)(yo + ty + 8 * i) * n + xo] = l;
    }
}

// ================= SGEMM 64x64x16 (head, N=128) — scalar ======================
__global__ __launch_bounds__(256) void sgemm64(
    const float* __restrict__ A, const float* __restrict__ B,
    const float* __restrict__ bias, float* __restrict__ C,
    int M, int N, int K)
{
    __shared__ float As[16][64];
    __shared__ float Bs[16][64];

    const int tid = threadIdx.x;
    const int tx = tid & 15;
    const int ty = tid >> 4;
    const int row0 = blockIdx.y * 64;
    const int col0 = blockIdx.x * 64;

    const int arow = tid >> 2;
    const int ak   = (tid & 3) << 2;
    const int bk   = tid >> 4;
    const int bcol = (tid & 15) << 2;

    const float* Ap = A + (long)(row0 + arow) * K + ak;
    const float* Bp = B + (long)bk * N + col0 + bcol;

    float acc[4][4];
#pragma unroll
    for (int i = 0; i < 4; i++)
#pragma unroll
        for (int j = 0; j < 4; j++) acc[i][j] = 0.f;

    for (int k0 = 0; k0 < K; k0 += 16) {
        float4 av = *(const float4*)(Ap + k0);
        float4 bv = *(const float4*)(Bp + (long)k0 * N);
        As[ak + 0][arow] = av.x;
        As[ak + 1][arow] = av.y;
        As[ak + 2][arow] = av.z;
        As[ak + 3][arow] = av.w;
        *(float4*)&Bs[bk][bcol] = bv;
        __syncthreads();
#pragma unroll
        for (int k = 0; k < 16; k++) {
            float a[4], b[4];
            *(float4*)&a[0] = *(const float4*)&As[k][ty * 4];
            *(float4*)&b[0] = *(const float4*)&Bs[k][tx * 4];
#pragma unroll
            for (int i = 0; i < 4; i++)
#pragma unroll
                for (int j = 0; j < 4; j++)
                    acc[i][j] = fmaf(a[i], b[j], acc[i][j]);
        }
        __syncthreads();
    }

#pragma unroll
    for (int i = 0; i < 4; i++) {
        int r = row0 + ty * 4 + i;
        int c = col0 + tx * 4;
        float4 v;
        v.x = acc[i][0] + bias[c + 0];
        v.y = acc[i][1] + bias[c + 1];
        v.z = acc[i][2] + bias[c + 2];
        v.w = acc[i][3] + bias[c + 3];
        *(float4*)&C[(long)r * N + c] = v;
    }
}

// ================= row L2-normalize + bf16 hi/lo emit =========================
__global__ __launch_bounds__(256) void normalize_kernel(
    float* __restrict__ f, __nv_bfloat16* __restrict__ fhi,
    __nv_bfloat16* __restrict__ flo)
{
    int row  = blockIdx.x * 8 + (threadIdx.x >> 5);
    int lane = threadIdx.x & 31;
    float4 v = ((const float4*)f)[row * 32 + lane];
    float s = v.x * v.x + v.y * v.y + v.z * v.z + v.w * v.w;
#pragma unroll
    for (int o = 16; o; o >>= 1) s += __shfl_xor_sync(0xffffffffu, s, o);
    float r = rsqrtf(s);
    v.x *= r; v.y *= r; v.z *= r; v.w *= r;
    ((float4*)f)[row * 32 + lane] = v;
    float vv[4] = {v.x, v.y, v.z, v.w};
    __nv_bfloat16 h[4], l[4];
#pragma unroll
    for (int j = 0; j < 4; j++) {
        h[j] = __float2bfloat16(vv[j]);
        l[j] = __float2bfloat16(vv[j] - __bfloat162float(h[j]));
    }
    *(uint2*)&fhi[row * 128 + lane * 4] = *(uint2*)h;
    *(uint2*)&flo[row * 128 + lane * 4] = *(uint2*)l;
}

// ================= positive-pair similarity + zero S ==========================
__global__ __launch_bounds__(256) void pos_kernel(
    const float* __restrict__ f, float* __restrict__ pos, float* __restrict__ S)
{
    int row  = blockIdx.x * 8 + (threadIdx.x >> 5);
    int lane = threadIdx.x & 31;
    int partner = (row + 4096) & 8191;
    float4 a = ((const float4*)f)[row * 32 + lane];
    float4 b = ((const float4*)f)[partner * 32 + lane];
    float s = a.x * b.x + a.y * b.y + a.z * b.z + a.w * b.w;
#pragma unroll
    for (int o = 16; o; o >>= 1) s += __shfl_xor_sync(0xffffffffu, s, o);
    if (lane == 0) { pos[row] = s * TINV; S[row] = 0.f; }
}

// ================= tensorized sim + sum-of-exp ================================
// grid (2, 64): CTA = 128 rows x 4096 cols (32 col tiles of 128).
// Rows (hi/lo) persistent in smem; col tiles 2-stage cp.async ring.
// Same warp layout / fragment mapping as gemm_mma, ROWB -> 272 (K=128).
#define ROW2 272
#define LAR  (128 * ROW2)           /* 34816 B per array */
#define LS_AH 0
#define LS_AL LAR
#define LS_BST (2 * LAR)            /* stage s at LS_BST + s*(2*LAR); BH then BL */
#define LS_RS  (6 * LAR)            /* rowsum [128][2] floats */
#define LOSS_SMEM (6 * LAR + 1024)  /* 209920 B */

__global__ __launch_bounds__(256) void loss_mma(
    const __nv_bfloat16* __restrict__ fhi, const __nv_bfloat16* __restrict__ flo,
    float* __restrict__ S)
{
    extern __shared__ char smem[];
    const unsigned int sb = smem_u32(smem);
    const int tid  = threadIdx.x;
    const int lane = tid & 31;
    const int wid  = tid >> 5;
    const int wm   = wid >> 1;
    const int wn   = wid & 1;
    const int r0   = blockIdx.y * 128;
    const int cbase = blockIdx.x * 4096;

    const int srow = tid >> 1;
    const int shal = tid & 1;
    const unsigned int sro = srow * ROW2 + shal * 128;

    // rows (persistent)
    {
        const __nv_bfloat16* gh = fhi + (long)(r0 + srow) * 128 + shal * 64;
        const __nv_bfloat16* gl = flo + (long)(r0 + srow) * 128 + shal * 64;
#pragma unroll
        for (int c = 0; c < 8; c++) {
            cp_async16(sb + LS_AH + sro + c * 16, gh + c * 8);
            cp_async16(sb + LS_AL + sro + c * 16, gl + c * 8);
        }
        cp_commit();
    }

#define LOAD_COL(s, ct) do { \
        unsigned int base = sb + LS_BST + (s) * (2 * LAR); \
        const __nv_bfloat16* gh = fhi + (long)(cbase + (ct) * 128 + srow) * 128 + shal * 64; \
        const __nv_bfloat16* gl = flo + (long)(cbase + (ct) * 128 + srow) * 128 + shal * 64; \
        _Pragma("unroll") \
        for (int c = 0; c < 8; c++) { \
            cp_async16(base + sro + c * 16, gh + c * 8); \
            cp_async16(base + LAR + sro + c * 16, gl + c * 8); \
        } \
        cp_commit(); \
    } while (0)

    LOAD_COL(0, 0);
    LOAD_COL(1, 1);

    float accS[4] = {0.f, 0.f, 0.f, 0.f};

    const unsigned int a_row  = lane & 15;
    const unsigned int a_koff = (lane >> 4) * 16;
    const unsigned int b_row  = (lane & 7) + ((lane >> 4) & 1) * 8;
    const unsigned int b_koff = ((lane >> 3) & 1) * 16;

    for (int ct = 0; ct < 32; ct++) {
        const unsigned int stg = sb + LS_BST + (ct & 1) * (2 * LAR);
        asm volatile("cp.async.wait_group 1;" ::: "memory");
        __syncthreads();

        float acc[2][8][4];
#pragma unroll
        for (int i = 0; i < 2; i++)
#pragma unroll
            for (int j = 0; j < 8; j++)
#pragma unroll
                for (int q = 0; q < 4; q++) acc[i][j][q] = 0.f;

#pragma unroll
        for (int s = 0; s < 8; s++) {
            const unsigned int kb = s * 32;
            unsigned int ah[2][4], al[2][4];
#pragma unroll
            for (int ma = 0; ma < 2; ma++) {
                unsigned int roff = (wm * 32 + ma * 16 + a_row) * ROW2 + kb + a_koff;
                ldmat4(ah[ma], sb + LS_AH + roff);
                ldmat4(al[ma], sb + LS_AL + roff);
            }
            unsigned int bh[4][4], bl[4][4];
#pragma unroll
            for (int nb = 0; nb < 4; nb++) {
                unsigned int roff = (wn * 64 + nb * 16 + b_row) * ROW2 + kb + b_koff;
                ldmat4(bh[nb], stg + roff);
                ldmat4(bl[nb], stg + LAR + roff);
            }
#pragma unroll
            for (int ma = 0; ma < 2; ma++)
#pragma unroll
                for (int na = 0; na < 8; na++) {
                    unsigned int h0 = bh[na >> 1][(na & 1) * 2];
                    unsigned int h1 = bh[na >> 1][(na & 1) * 2 + 1];
                    unsigned int l0 = bl[na >> 1][(na & 1) * 2];
                    unsigned int l1 = bl[na >> 1][(na & 1) * 2 + 1];
                    mma16816(acc[ma][na], ah[ma], h0, h1);
                    mma16816(acc[ma][na], ah[ma], l0, l1);
                    mma16816(acc[ma][na], al[ma], h0, h1);
                }
        }

        // epilogue: exp + masked accumulate
        const int c0 = cbase + ct * 128;
#pragma unroll
        for (int ma = 0; ma < 2; ma++) {
            int gi1 = r0 + wm * 32 + ma * 16 + (lane >> 2);
            int gi2 = gi1 + 8;
#pragma unroll
            for (int na = 0; na < 8; na++) {
                int gj = c0 + wn * 64 + na * 8 + (lane & 3) * 2;
                float e0 = exp2f(fmaf(acc[ma][na][0], K1E, -K1E));
                float e1 = exp2f(fmaf(acc[ma][na][1], K1E, -K1E));
                float e2 = exp2f(fmaf(acc[ma][na][2], K1E, -K1E));
                float e3 = exp2f(fmaf(acc[ma][na][3], K1E, -K1E));
                accS[ma * 2 + 0] += ((gi1 != gj)     ? e0 : 0.f)
                                  + ((gi1 != gj + 1) ? e1 : 0.f);
                accS[ma * 2 + 1] += ((gi2 != gj)     ? e2 : 0.f)
                                  + ((gi2 != gj + 1) ? e3 : 0.f);
            }
        }

        __syncthreads();
        if (ct + 2 < 32) LOAD_COL(ct & 1, ct + 2);
        else cp_commit();
    }

    // cross-lane reduction (lanes sharing lane>>2 hold the same rows)
#pragma unroll
    for (int i = 0; i < 4; i++) {
        accS[i] += __shfl_xor_sync(0xffffffffu, accS[i], 1);
        accS[i] += __shfl_xor_sync(0xffffffffu, accS[i], 2);
    }
    __syncthreads();
    float* rs = (float*)(smem + LS_RS);
    if ((lane & 3) == 0) {
#pragma unroll
        for (int i = 0; i < 4; i++) {
            int rloc = wm * 32 + (i >> 1) * 16 + (i & 1) * 8 + (lane >> 2);
            rs[rloc * 2 + wn] = accS[i];
        }
    }
    __syncthreads();
    if (tid < 128)
        atomicAdd(&S[r0 + tid], rs[tid * 2] + rs[tid * 2 + 1]);
#undef LOAD_COL
}

// ================= final deterministic reduction ==============================
__global__ __launch_bounds__(256) void final_kernel(
    const float* __restrict__ S, const float* __restrict__ pos,
    float* __restrict__ out)
{
    __shared__ float sm[256];
    float v = 0.f;
    for (int i = threadIdx.x; i < 8192; i += 256)
        v += TINV + logf(S[i]) - pos[i];
    sm[threadIdx.x] = v;
    __syncthreads();
    for (int o = 128; o; o >>= 1) {
        if (threadIdx.x < o) sm[threadIdx.x] += sm[threadIdx.x + o];
        __syncthreads();
    }
    if (threadIdx.x == 0) out[0] = sm[0] * (1.0f / 8192.0f);
}

// ================= launch =====================================================
extern "C" void kernel_launch(void* const* d_in, const int* in_sizes, int n_in,
                              void* d_out, int out_size)
{
    const float* x[2] = {(const float*)d_in[0], (const float*)d_in[1]};
    const float* W0 = (const float*)d_in[2];
    const float* b0 = (const float*)d_in[3];
    const float* W1 = (const float*)d_in[4];
    const float* b1 = (const float*)d_in[5];
    const float* W2 = (const float*)d_in[6];
    const float* b2 = (const float*)d_in[7];
    float* out = (float*)d_out;

    __nv_bfloat16 *xhi, *xlo, *w0h, *w0l, *w1h, *w1l, *a0h, *a0l, *fhi, *flo;
    float *act1, *feat, *pos, *S;
    cudaGetSymbolAddress((void**)&xhi, g_xhi);
    cudaGetSymbolAddress((void**)&xlo, g_xlo);
    cudaGetSymbolAddress((void**)&w0h, g_w0h);
    cudaGetSymbolAddress((void**)&w0l, g_w0l);
    cudaGetSymbolAddress((void**)&w1h, g_w1h);
    cudaGetSymbolAddress((void**)&w1l, g_w1l);
    cudaGetSymbolAddress((void**)&a0h, g_a0h);
    cudaGetSymbolAddress((void**)&a0l, g_a0l);
    cudaGetSymbolAddress((void**)&fhi, g_fhi);
    cudaGetSymbolAddress((void**)&flo, g_flo);
    cudaGetSymbolAddress((void**)&act1, g_act1);
    cudaGetSymbolAddress((void**)&feat, g_feat);
    cudaGetSymbolAddress((void**)&pos, g_pos);
    cudaGetSymbolAddress((void**)&S, g_S);

    cudaFuncSetAttribute(gemm_mma<true, true>,
                         cudaFuncAttributeMaxDynamicSharedMemorySize, GEMM_SMEM);
    cudaFuncSetAttribute(gemm_mma<false, false>,
                         cudaFuncAttributeMaxDynamicSharedMemorySize, GEMM_SMEM);
    cudaFuncSetAttribute(loss_mma,
                         cudaFuncAttributeMaxDynamicSharedMemorySize, LOSS_SMEM);

    dim3 gT(64, 64);
    tsplit_kernel<<<gT, 256>>>(W0, w0h, w0l);
    tsplit_kernel<<<gT, 256>>>(W1, w1h, w1l);

    dim3 gG(32, 16);
    dim3 gSmall(128 / 64, 4096 / 64);

    for (int v = 0; v < 2; v++) {
        split_kernel<<<(4096 * 2048 / 4) / 256, 256>>>(
            (const float4*)x[v], (uint2*)xhi, (uint2*)xlo);
        gemm_mma<true, true><<<gG, 256, GEMM_SMEM>>>(
            xhi, xlo, w0h, w0l, b0, a0h, a0l, (float*)0);
        gemm_mma<false, false><<<gG, 256, GEMM_SMEM>>>(
            a0h, a0l, w1h, w1l, b1, (__nv_bfloat16*)0, (__nv_bfloat16*)0, act1);
        sgemm64<<<gSmall, 256>>>(act1, W2, b2, feat + (long)v * 4096 * 128,
                                 4096, 128, 2048);
    }
    normalize_kernel<<<1024, 256>>>(feat, fhi, flo);
    pos_kernel<<<1024, 256>>>(feat, pos, S);
    loss_mma<<<dim3(2, 64), 256, LOSS_SMEM>>>(fhi, flo, S);
    final_kernel<<<1, 256>>>(S, pos, out);
}

// round 7
// speedup vs baseline: 3.0694x; 1.2646x over previous
#include <cuda_runtime.h>
#include <cuda_bf16.h>
#include <stdint.h>
#include <math.h>

#define TINV 14.2857142857142857f   /* 1 / 0.07 */
#define K1E  20.6099291083577f      /* TINV * log2(e) */

// -------- scratch (no allocations allowed) --------
static __device__ __nv_bfloat16 g_xhi[8192 * 2048];   // 32 MB
static __device__ __nv_bfloat16 g_xlo[8192 * 2048];
static __device__ __nv_bfloat16 g_w0h[2048 * 2048];
static __device__ __nv_bfloat16 g_w0l[2048 * 2048];
static __device__ __nv_bfloat16 g_w1h[2048 * 2048];
static __device__ __nv_bfloat16 g_w1l[2048 * 2048];
static __device__ __nv_bfloat16 g_w2h[128 * 2048];
static __device__ __nv_bfloat16 g_w2l[128 * 2048];
static __device__ __nv_bfloat16 g_a0h[8192 * 2048];
static __device__ __nv_bfloat16 g_a0l[8192 * 2048];
static __device__ __nv_bfloat16 g_a1h[8192 * 2048];
static __device__ __nv_bfloat16 g_a1l[8192 * 2048];
static __device__ float g_feat[8192 * 128];
static __device__ __nv_bfloat16 g_fhi[8192 * 128];
static __device__ __nv_bfloat16 g_flo[8192 * 128];
static __device__ float g_pos[8192];
static __device__ float g_S[8192];

// ======================= PTX helpers (baseline ISA only) =====================
__device__ __forceinline__ void cp_async16(unsigned int saddr, const void* gptr) {
    asm volatile("cp.async.ca.shared.global [%0], [%1], 16;" :: "r"(saddr), "l"(gptr));
}
__device__ __forceinline__ void cp_commit() {
    asm volatile("cp.async.commit_group;");
}
__device__ __forceinline__ unsigned int smem_u32(const void* p) {
    unsigned int a;
    asm("{ .reg .u64 t; cvta.to.shared.u64 t, %1; cvt.u32.u64 %0, t; }" : "=r"(a) : "l"(p));
    return a;
}
__device__ __forceinline__ void ldmat4(unsigned int* r, unsigned int addr) {
    asm volatile("ldmatrix.sync.aligned.m8n8.x4.shared.b16 {%0,%1,%2,%3}, [%4];"
        : "=r"(r[0]), "=r"(r[1]), "=r"(r[2]), "=r"(r[3]) : "r"(addr));
}
__device__ __forceinline__ void mma16816(float* d, const unsigned int* a,
                                         unsigned int b0, unsigned int b1) {
    asm volatile(
        "mma.sync.aligned.m16n8k16.row.col.f32.bf16.bf16.f32 "
        "{%0,%1,%2,%3}, {%4,%5,%6,%7}, {%8,%9}, {%0,%1,%2,%3};"
        : "+f"(d[0]), "+f"(d[1]), "+f"(d[2]), "+f"(d[3])
        : "r"(a[0]), "r"(a[1]), "r"(a[2]), "r"(a[3]), "r"(b0), "r"(b1));
}

// ======================= bf16-split warp-MMA GEMM (128x128) ==================
#define ROWB 80
#define OFF_AH 0
#define OFF_AL (128 * ROWB)
#define OFF_BH (2 * 128 * ROWB)
#define OFF_BL (3 * 128 * ROWB)
#define STAGE  (4 * 128 * ROWB)     /* 40960 B */
#define SMEM_BIAS 0
#define SMEM_STAGE0 1024
#define GEMM_SMEM (SMEM_STAGE0 + 2 * STAGE)   /* 82944 B */

template <bool RELU, bool OUT_PAIR>
__global__ __launch_bounds__(256, 2) void gemm_mma(
    const __nv_bfloat16* __restrict__ Ahi, const __nv_bfloat16* __restrict__ Alo,
    const __nv_bfloat16* __restrict__ Bhi, const __nv_bfloat16* __restrict__ Blo,
    const float* __restrict__ bias,
    __nv_bfloat16* __restrict__ Chi, __nv_bfloat16* __restrict__ Clo,
    float* __restrict__ Cf)
{
    extern __shared__ char smem[];
    const unsigned int sb = smem_u32(smem);
    const int tid  = threadIdx.x;
    const int lane = tid & 31;
    const int wid  = tid >> 5;
    const int wm   = wid >> 1;
    const int wn   = wid & 1;
    const int row0 = blockIdx.x * 128;
    const int col0 = blockIdx.y * 128;
    const int K = 2048;
    const int NKT = 64;

    if (tid < 128) ((float*)(smem + SMEM_BIAS))[tid] = bias[col0 + tid];

    const int srow = tid >> 1;
    const int shal = tid & 1;
    const __nv_bfloat16* gAh = Ahi + (long)(row0 + srow) * K + shal * 16;
    const __nv_bfloat16* gAl = Alo + (long)(row0 + srow) * K + shal * 16;
    const __nv_bfloat16* gBh = Bhi + (long)(col0 + srow) * K + shal * 16;
    const __nv_bfloat16* gBl = Blo + (long)(col0 + srow) * K + shal * 16;
    const unsigned int sro = srow * ROWB + shal * 32;

#define LOAD_STAGE(stg, k0) do { \
        cp_async16((stg) + OFF_AH + sro,      gAh + (k0)); \
        cp_async16((stg) + OFF_AH + sro + 16, gAh + (k0) + 8); \
        cp_async16((stg) + OFF_AL + sro,      gAl + (k0)); \
        cp_async16((stg) + OFF_AL + sro + 16, gAl + (k0) + 8); \
        cp_async16((stg) + OFF_BH + sro,      gBh + (k0)); \
        cp_async16((stg) + OFF_BH + sro + 16, gBh + (k0) + 8); \
        cp_async16((stg) + OFF_BL + sro,      gBl + (k0)); \
        cp_async16((stg) + OFF_BL + sro + 16, gBl + (k0) + 8); \
    } while (0)

#pragma unroll
    for (int b = 0; b < 2; b++) {
        LOAD_STAGE(sb + SMEM_STAGE0 + b * STAGE, b * 32);
        cp_commit();
    }

    float acc[2][8][4];
#pragma unroll
    for (int i = 0; i < 2; i++)
#pragma unroll
        for (int j = 0; j < 8; j++)
#pragma unroll
            for (int q = 0; q < 4; q++) acc[i][j][q] = 0.f;

    const unsigned int a_row  = lane & 15;
    const unsigned int a_koff = (lane >> 4) * 16;
    const unsigned int b_row  = (lane & 7) + ((lane >> 4) & 1) * 8;
    const unsigned int b_koff = ((lane >> 3) & 1) * 16;

    for (int kt = 0; kt < NKT; kt++) {
        const unsigned int stg = sb + SMEM_STAGE0 + (kt & 1) * STAGE;
        asm volatile("cp.async.wait_group 1;" ::: "memory");
        __syncthreads();

#pragma unroll
        for (int s = 0; s < 2; s++) {
            const unsigned int kb = s * 32;
            unsigned int ah[2][4], al[2][4];
#pragma unroll
            for (int ma = 0; ma < 2; ma++) {
                unsigned int roff = (wm * 32 + ma * 16 + a_row) * ROWB + kb + a_koff;
                ldmat4(ah[ma], stg + OFF_AH + roff);
                ldmat4(al[ma], stg + OFF_AL + roff);
            }
            unsigned int bh[4][4], bl[4][4];
#pragma unroll
            for (int nb = 0; nb < 4; nb++) {
                unsigned int roff = (wn * 64 + nb * 16 + b_row) * ROWB + kb + b_koff;
                ldmat4(bh[nb], stg + OFF_BH + roff);
                ldmat4(bl[nb], stg + OFF_BL + roff);
            }
#pragma unroll
            for (int ma = 0; ma < 2; ma++)
#pragma unroll
                for (int na = 0; na < 8; na++) {
                    unsigned int h0 = bh[na >> 1][(na & 1) * 2];
                    unsigned int h1 = bh[na >> 1][(na & 1) * 2 + 1];
                    unsigned int l0 = bl[na >> 1][(na & 1) * 2];
                    unsigned int l1 = bl[na >> 1][(na & 1) * 2 + 1];
                    mma16816(acc[ma][na], ah[ma], h0, h1);
                    mma16816(acc[ma][na], ah[ma], l0, l1);
                    mma16816(acc[ma][na], al[ma], h0, h1);
                }
        }

        __syncthreads();
        if (kt + 2 < NKT) LOAD_STAGE(stg, (kt + 2) * 32);
        cp_commit();
    }

    const float* bs = (const float*)(smem + SMEM_BIAS);
    const int ccol = wn * 64;
#pragma unroll
    for (int ma = 0; ma < 2; ma++) {
#pragma unroll
        for (int na = 0; na < 8; na++) {
            int c  = ccol + na * 8 + (lane & 3) * 2;
            int r1 = row0 + wm * 32 + ma * 16 + (lane >> 2);
            int r2 = r1 + 8;
            float v0 = acc[ma][na][0] + bs[c];
            float v1 = acc[ma][na][1] + bs[c + 1];
            float v2 = acc[ma][na][2] + bs[c];
            float v3 = acc[ma][na][3] + bs[c + 1];
            if (RELU) {
                v0 = fmaxf(v0, 0.f); v1 = fmaxf(v1, 0.f);
                v2 = fmaxf(v2, 0.f); v3 = fmaxf(v3, 0.f);
            }
            long o1 = (long)r1 * 2048 + col0 + c;
            long o2 = (long)r2 * 2048 + col0 + c;
            if (OUT_PAIR) {
                __nv_bfloat16 h0 = __float2bfloat16(v0);
                __nv_bfloat16 h1 = __float2bfloat16(v1);
                __nv_bfloat16 h2 = __float2bfloat16(v2);
                __nv_bfloat16 h3 = __float2bfloat16(v3);
                __nv_bfloat162 hp1 = {h0, h1}, hp2 = {h2, h3};
                __nv_bfloat162 lp1 = {__float2bfloat16(v0 - __bfloat162float(h0)),
                                      __float2bfloat16(v1 - __bfloat162float(h1))};
                __nv_bfloat162 lp2 = {__float2bfloat16(v2 - __bfloat162float(h2)),
                                      __float2bfloat16(v3 - __bfloat162float(h3))};
                *(__nv_bfloat162*)&Chi[o1] = hp1;
                *(__nv_bfloat162*)&Chi[o2] = hp2;
                *(__nv_bfloat162*)&Clo[o1] = lp1;
                *(__nv_bfloat162*)&Clo[o2] = lp2;
            } else {
                *(float2*)&Cf[o1] = make_float2(v0, v1);
                *(float2*)&Cf[o2] = make_float2(v2, v3);
            }
        }
    }
#undef LOAD_STAGE
}

// ======================= head GEMM: M-tile 64, N=128 (feat out) ==============
// CTA 64x128, 8 warps 2(m)x4(n), warp tile 32x32, k-chunk 32, 2 stages.
#define H_AH 0
#define H_AL (64 * ROWB)            /* 5120 */
#define H_BH (2 * 64 * ROWB)        /* 10240 */
#define H_BL (H_BH + 128 * ROWB)    /* 20480 */
#define H_STAGE (H_BH + 2 * 128 * ROWB)  /* 30720 */
#define HEAD_SMEM (1024 + 2 * H_STAGE)   /* 62464 */

__global__ __launch_bounds__(256, 2) void gemm_head(
    const __nv_bfloat16* __restrict__ Ahi, const __nv_bfloat16* __restrict__ Alo,
    const __nv_bfloat16* __restrict__ Bhi, const __nv_bfloat16* __restrict__ Blo,
    const float* __restrict__ bias, float* __restrict__ Cf)
{
    extern __shared__ char smem[];
    const unsigned int sb = smem_u32(smem);
    const int tid  = threadIdx.x;
    const int lane = tid & 31;
    const int wid  = tid >> 5;
    const int wm   = wid >> 2;          // 0..1
    const int wn   = wid & 3;           // 0..3
    const int row0 = blockIdx.y * 64;
    const int K = 2048;
    const int NKT = 64;

    if (tid < 128) ((float*)(smem + SMEM_BIAS))[tid] = bias[tid];

    // A staging: 64 rows x 64B, thread -> (row tid>>2, 16B quarter tid&3)
    const int sar = tid >> 2;
    const int saq = tid & 3;
    const __nv_bfloat16* gAh = Ahi + (long)(row0 + sar) * K + saq * 8;
    const __nv_bfloat16* gAl = Alo + (long)(row0 + sar) * K + saq * 8;
    const unsigned int sra = sar * ROWB + saq * 16;
    // B staging: 128 rows x 64B, thread -> (row tid>>1, 32B half tid&1)
    const int sbr = tid >> 1;
    const int sbh = tid & 1;
    const __nv_bfloat16* gBh = Bhi + (long)sbr * K + sbh * 16;
    const __nv_bfloat16* gBl = Blo + (long)sbr * K + sbh * 16;
    const unsigned int srb = sbr * ROWB + sbh * 32;

#define H_LOAD(stg, k0) do { \
        cp_async16((stg) + H_AH + sra, gAh + (k0)); \
        cp_async16((stg) + H_AL + sra, gAl + (k0)); \
        cp_async16((stg) + H_BH + srb,      gBh + (k0)); \
        cp_async16((stg) + H_BH + srb + 16, gBh + (k0) + 8); \
        cp_async16((stg) + H_BL + srb,      gBl + (k0)); \
        cp_async16((stg) + H_BL + srb + 16, gBl + (k0) + 8); \
    } while (0)

#pragma unroll
    for (int b = 0; b < 2; b++) {
        H_LOAD(sb + SMEM_STAGE0 + b * H_STAGE, b * 32);
        cp_commit();
    }

    float acc[2][4][4];
#pragma unroll
    for (int i = 0; i < 2; i++)
#pragma unroll
        for (int j = 0; j < 4; j++)
#pragma unroll
            for (int q = 0; q < 4; q++) acc[i][j][q] = 0.f;

    const unsigned int a_row  = lane & 15;
    const unsigned int a_koff = (lane >> 4) * 16;
    const unsigned int b_row  = (lane & 7) + ((lane >> 4) & 1) * 8;
    const unsigned int b_koff = ((lane >> 3) & 1) * 16;

    for (int kt = 0; kt < NKT; kt++) {
        const unsigned int stg = sb + SMEM_STAGE0 + (kt & 1) * H_STAGE;
        asm volatile("cp.async.wait_group 1;" ::: "memory");
        __syncthreads();

#pragma unroll
        for (int s = 0; s < 2; s++) {
            const unsigned int kb = s * 32;
            unsigned int ah[2][4], al[2][4];
#pragma unroll
            for (int ma = 0; ma < 2; ma++) {
                unsigned int roff = (wm * 32 + ma * 16 + a_row) * ROWB + kb + a_koff;
                ldmat4(ah[ma], stg + H_AH + roff);
                ldmat4(al[ma], stg + H_AL + roff);
            }
            unsigned int bh[2][4], bl[2][4];
#pragma unroll
            for (int nb = 0; nb < 2; nb++) {
                unsigned int roff = (wn * 32 + nb * 16 + b_row) * ROWB + kb + b_koff;
                ldmat4(bh[nb], stg + H_BH + roff);
                ldmat4(bl[nb], stg + H_BL + roff);
            }
#pragma unroll
            for (int ma = 0; ma < 2; ma++)
#pragma unroll
                for (int na = 0; na < 4; na++) {
                    unsigned int h0 = bh[na >> 1][(na & 1) * 2];
                    unsigned int h1 = bh[na >> 1][(na & 1) * 2 + 1];
                    unsigned int l0 = bl[na >> 1][(na & 1) * 2];
                    unsigned int l1 = bl[na >> 1][(na & 1) * 2 + 1];
                    mma16816(acc[ma][na], ah[ma], h0, h1);
                    mma16816(acc[ma][na], ah[ma], l0, l1);
                    mma16816(acc[ma][na], al[ma], h0, h1);
                }
        }

        __syncthreads();
        if (kt + 2 < NKT) H_LOAD(stg, (kt + 2) * 32);
        cp_commit();
    }

    const float* bs = (const float*)(smem + SMEM_BIAS);
#pragma unroll
    for (int ma = 0; ma < 2; ma++) {
#pragma unroll
        for (int na = 0; na < 4; na++) {
            int c  = wn * 32 + na * 8 + (lane & 3) * 2;
            int r1 = row0 + wm * 32 + ma * 16 + (lane >> 2);
            int r2 = r1 + 8;
            *(float2*)&Cf[(long)r1 * 128 + c] =
                make_float2(acc[ma][na][0] + bs[c], acc[ma][na][1] + bs[c + 1]);
            *(float2*)&Cf[(long)r2 * 128 + c] =
                make_float2(acc[ma][na][2] + bs[c], acc[ma][na][3] + bs[c + 1]);
        }
    }
#undef H_LOAD
}

// ======================= fp32 -> bf16 hi/lo split =============================
__global__ __launch_bounds__(256) void split_kernel(
    const float4* __restrict__ in, uint2* __restrict__ hi, uint2* __restrict__ lo)
{
    int i = blockIdx.x * 256 + threadIdx.x;
    float4 v = in[i];
    __nv_bfloat16 h[4], l[4];
    float vv[4] = {v.x, v.y, v.z, v.w};
#pragma unroll
    for (int j = 0; j < 4; j++) {
        h[j] = __float2bfloat16(vv[j]);
        l[j] = __float2bfloat16(vv[j] - __bfloat162float(h[j]));
    }
    hi[i] = *(uint2*)h;
    lo[i] = *(uint2*)l;
}

// ============== W [R,C] -> W^T hi/lo bf16 [C,R] ===============================
__global__ __launch_bounds__(256) void tsplit_kernel(
    const float* __restrict__ W, __nv_bfloat16* __restrict__ Th,
    __nv_bfloat16* __restrict__ Tl, int R, int C)
{
    __shared__ float t[32][33];
    int lane = threadIdx.x % 32;
    int ty = threadIdx.x / 32;
    int x = blockIdx.x * 32 + lane;       // col in W
    int y0 = blockIdx.y * 32;             // row in W
#pragma unroll
    for (int i = 0; i < 4; i++)
        t[ty + 8 * i][lane] = W[(long)(y0 + ty + 8 * i) * C + x];
    __syncthreads();
    int xo = y0 + lane;                   // col in out (= row of W)
    int yo = blockIdx.x * 32;             // row in out (= col of W)
#pragma unroll
    for (int i = 0; i < 4; i++) {
        float v = t[lane][ty + 8 * i];
        __nv_bfloat16 h = __float2bfloat16(v);
        __nv_bfloat16 l = __float2bfloat16(v - __bfloat162float(h));
        Th[(long)(yo + ty + 8 * i) * R + xo] = h;
        Tl[(long)(yo + ty + 8 * i) * R + xo] = l;
    }
}

// ================= row L2-normalize + bf16 hi/lo emit =========================
__global__ __launch_bounds__(256) void normalize_kernel(
    float* __restrict__ f, __nv_bfloat16* __restrict__ fhi,
    __nv_bfloat16* __restrict__ flo)
{
    int row  = blockIdx.x * 8 + (threadIdx.x >> 5);
    int lane = threadIdx.x & 31;
    float4 v = ((const float4*)f)[row * 32 + lane];
    float s = v.x * v.x + v.y * v.y + v.z * v.z + v.w * v.w;
#pragma unroll
    for (int o = 16; o; o >>= 1) s += __shfl_xor_sync(0xffffffffu, s, o);
    float r = rsqrtf(s);
    v.x *= r; v.y *= r; v.z *= r; v.w *= r;
    ((float4*)f)[row * 32 + lane] = v;
    float vv[4] = {v.x, v.y, v.z, v.w};
    __nv_bfloat16 h[4], l[4];
#pragma unroll
    for (int j = 0; j < 4; j++) {
        h[j] = __float2bfloat16(vv[j]);
        l[j] = __float2bfloat16(vv[j] - __bfloat162float(h[j]));
    }
    *(uint2*)&fhi[row * 128 + lane * 4] = *(uint2*)h;
    *(uint2*)&flo[row * 128 + lane * 4] = *(uint2*)l;
}

// ================= positive-pair similarity + zero S ==========================
__global__ __launch_bounds__(256) void pos_kernel(
    const float* __restrict__ f, float* __restrict__ pos, float* __restrict__ S)
{
    int row  = blockIdx.x * 8 + (threadIdx.x >> 5);
    int lane = threadIdx.x & 31;
    int partner = (row + 4096) & 8191;
    float4 a = ((const float4*)f)[row * 32 + lane];
    float4 b = ((const float4*)f)[partner * 32 + lane];
    float s = a.x * b.x + a.y * b.y + a.z * b.z + a.w * b.w;
#pragma unroll
    for (int o = 16; o; o >>= 1) s += __shfl_xor_sync(0xffffffffu, s, o);
    if (lane == 0) { pos[row] = s * TINV; S[row] = 0.f; }
}

// ================= tensorized sim + sum-of-exp ================================
#define ROW2 272
#define LAR  (128 * ROW2)
#define LS_AH 0
#define LS_AL LAR
#define LS_BST (2 * LAR)
#define LS_RS  (6 * LAR)
#define LOSS_SMEM (6 * LAR + 1024)

__global__ __launch_bounds__(256) void loss_mma(
    const __nv_bfloat16* __restrict__ fhi, const __nv_bfloat16* __restrict__ flo,
    float* __restrict__ S)
{
    extern __shared__ char smem[];
    const unsigned int sb = smem_u32(smem);
    const int tid  = threadIdx.x;
    const int lane = tid & 31;
    const int wid  = tid >> 5;
    const int wm   = wid >> 1;
    const int wn   = wid & 1;
    const int r0   = blockIdx.y * 128;
    const int cbase = blockIdx.x * 4096;

    const int srow = tid >> 1;
    const int shal = tid & 1;
    const unsigned int sro = srow * ROW2 + shal * 128;

    {
        const __nv_bfloat16* gh = fhi + (long)(r0 + srow) * 128 + shal * 64;
        const __nv_bfloat16* gl = flo + (long)(r0 + srow) * 128 + shal * 64;
#pragma unroll
        for (int c = 0; c < 8; c++) {
            cp_async16(sb + LS_AH + sro + c * 16, gh + c * 8);
            cp_async16(sb + LS_AL + sro + c * 16, gl + c * 8);
        }
        cp_commit();
    }

#define LOAD_COL(s, ct) do { \
        unsigned int base = sb + LS_BST + (s) * (2 * LAR); \
        const __nv_bfloat16* gh = fhi + (long)(cbase + (ct) * 128 + srow) * 128 + shal * 64; \
        const __nv_bfloat16* gl = flo + (long)(cbase + (ct) * 128 + srow) * 128 + shal * 64; \
        _Pragma("unroll") \
        for (int c = 0; c < 8; c++) { \
            cp_async16(base + sro + c * 16, gh + c * 8); \
            cp_async16(base + LAR + sro + c * 16, gl + c * 8); \
        } \
        cp_commit(); \
    } while (0)

    LOAD_COL(0, 0);
    LOAD_COL(1, 1);

    float accS[4] = {0.f, 0.f, 0.f, 0.f};

    const unsigned int a_row  = lane & 15;
    const unsigned int a_koff = (lane >> 4) * 16;
    const unsigned int b_row  = (lane & 7) + ((lane >> 4) & 1) * 8;
    const unsigned int b_koff = ((lane >> 3) & 1) * 16;

    for (int ct = 0; ct < 32; ct++) {
        const unsigned int stg = sb + LS_BST + (ct & 1) * (2 * LAR);
        asm volatile("cp.async.wait_group 1;" ::: "memory");
        __syncthreads();

        float acc[2][8][4];
#pragma unroll
        for (int i = 0; i < 2; i++)
#pragma unroll
            for (int j = 0; j < 8; j++)
#pragma unroll
                for (int q = 0; q < 4; q++) acc[i][j][q] = 0.f;

#pragma unroll
        for (int s = 0; s < 8; s++) {
            const unsigned int kb = s * 32;
            unsigned int ah[2][4], al[2][4];
#pragma unroll
            for (int ma = 0; ma < 2; ma++) {
                unsigned int roff = (wm * 32 + ma * 16 + a_row) * ROW2 + kb + a_koff;
                ldmat4(ah[ma], sb + LS_AH + roff);
                ldmat4(al[ma], sb + LS_AL + roff);
            }
            unsigned int bh[4][4], bl[4][4];
#pragma unroll
            for (int nb = 0; nb < 4; nb++) {
                unsigned int roff = (wn * 64 + nb * 16 + b_row) * ROW2 + kb + b_koff;
                ldmat4(bh[nb], stg + roff);
                ldmat4(bl[nb], stg + LAR + roff);
            }
#pragma unroll
            for (int ma = 0; ma < 2; ma++)
#pragma unroll
                for (int na = 0; na < 8; na++) {
                    unsigned int h0 = bh[na >> 1][(na & 1) * 2];
                    unsigned int h1 = bh[na >> 1][(na & 1) * 2 + 1];
                    unsigned int l0 = bl[na >> 1][(na & 1) * 2];
                    unsigned int l1 = bl[na >> 1][(na & 1) * 2 + 1];
                    mma16816(acc[ma][na], ah[ma], h0, h1);
                    mma16816(acc[ma][na], ah[ma], l0, l1);
                    mma16816(acc[ma][na], al[ma], h0, h1);
                }
        }

        const int c0 = cbase + ct * 128;
#pragma unroll
        for (int ma = 0; ma < 2; ma++) {
            int gi1 = r0 + wm * 32 + ma * 16 + (lane >> 2);
            int gi2 = gi1 + 8;
#pragma unroll
            for (int na = 0; na < 8; na++) {
                int gj = c0 + wn * 64 + na * 8 + (lane & 3) * 2;
                float e0 = exp2f(fmaf(acc[ma][na][0], K1E, -K1E));
                float e1 = exp2f(fmaf(acc[ma][na][1], K1E, -K1E));
                float e2 = exp2f(fmaf(acc[ma][na][2], K1E, -K1E));
                float e3 = exp2f(fmaf(acc[ma][na][3], K1E, -K1E));
                accS[ma * 2 + 0] += ((gi1 != gj)     ? e0 : 0.f)
                                  + ((gi1 != gj + 1) ? e1 : 0.f);
                accS[ma * 2 + 1] += ((gi2 != gj)     ? e2 : 0.f)
                                  + ((gi2 != gj + 1) ? e3 : 0.f);
            }
        }

        __syncthreads();
        if (ct + 2 < 32) LOAD_COL(ct & 1, ct + 2);
        else cp_commit();
    }

#pragma unroll
    for (int i = 0; i < 4; i++) {
        accS[i] += __shfl_xor_sync(0xffffffffu, accS[i], 1);
        accS[i] += __shfl_xor_sync(0xffffffffu, accS[i], 2);
    }
    __syncthreads();
    float* rs = (float*)(smem + LS_RS);
    if ((lane & 3) == 0) {
#pragma unroll
        for (int i = 0; i < 4; i++) {
            int rloc = wm * 32 + (i >> 1) * 16 + (i & 1) * 8 + (lane >> 2);
            rs[rloc * 2 + wn] = accS[i];
        }
    }
    __syncthreads();
    if (tid < 128)
        atomicAdd(&S[r0 + tid], rs[tid * 2] + rs[tid * 2 + 1]);
#undef LOAD_COL
}

// ================= final deterministic reduction ==============================
__global__ __launch_bounds__(256) void final_kernel(
    const float* __restrict__ S, const float* __restrict__ pos,
    float* __restrict__ out)
{
    __shared__ float sm[256];
    float v = 0.f;
    for (int i = threadIdx.x; i < 8192; i += 256)
        v += TINV + logf(S[i]) - pos[i];
    sm[threadIdx.x] = v;
    __syncthreads();
    for (int o = 128; o; o >>= 1) {
        if (threadIdx.x < o) sm[threadIdx.x] += sm[threadIdx.x + o];
        __syncthreads();
    }
    if (threadIdx.x == 0) out[0] = sm[0] * (1.0f / 8192.0f);
}

// ================= launch =====================================================
extern "C" void kernel_launch(void* const* d_in, const int* in_sizes, int n_in,
                              void* d_out, int out_size)
{
    const float* x1 = (const float*)d_in[0];
    const float* x2 = (const float*)d_in[1];
    const float* W0 = (const float*)d_in[2];
    const float* b0 = (const float*)d_in[3];
    const float* W1 = (const float*)d_in[4];
    const float* b1 = (const float*)d_in[5];
    const float* W2 = (const float*)d_in[6];
    const float* b2 = (const float*)d_in[7];
    float* out = (float*)d_out;

    __nv_bfloat16 *xhi, *xlo, *w0h, *w0l, *w1h, *w1l, *w2h, *w2l;
    __nv_bfloat16 *a0h, *a0l, *a1h, *a1l, *fhi, *flo;
    float *feat, *pos, *S;
    cudaGetSymbolAddress((void**)&xhi, g_xhi);
    cudaGetSymbolAddress((void**)&xlo, g_xlo);
    cudaGetSymbolAddress((void**)&w0h, g_w0h);
    cudaGetSymbolAddress((void**)&w0l, g_w0l);
    cudaGetSymbolAddress((void**)&w1h, g_w1h);
    cudaGetSymbolAddress((void**)&w1l, g_w1l);
    cudaGetSymbolAddress((void**)&w2h, g_w2h);
    cudaGetSymbolAddress((void**)&w2l, g_w2l);
    cudaGetSymbolAddress((void**)&a0h, g_a0h);
    cudaGetSymbolAddress((void**)&a0l, g_a0l);
    cudaGetSymbolAddress((void**)&a1h, g_a1h);
    cudaGetSymbolAddress((void**)&a1l, g_a1l);
    cudaGetSymbolAddress((void**)&fhi, g_fhi);
    cudaGetSymbolAddress((void**)&flo, g_flo);
    cudaGetSymbolAddress((void**)&feat, g_feat);
    cudaGetSymbolAddress((void**)&pos, g_pos);
    cudaGetSymbolAddress((void**)&S, g_S);

    cudaFuncSetAttribute(gemm_mma<true, true>,
                         cudaFuncAttributeMaxDynamicSharedMemorySize, GEMM_SMEM);
    cudaFuncSetAttribute(gemm_mma<false, true>,
                         cudaFuncAttributeMaxDynamicSharedMemorySize, GEMM_SMEM);
    cudaFuncSetAttribute(gemm_head,
                         cudaFuncAttributeMaxDynamicSharedMemorySize, HEAD_SMEM);
    cudaFuncSetAttribute(loss_mma,
                         cudaFuncAttributeMaxDynamicSharedMemorySize, LOSS_SMEM);

    // weight transpose + split
    tsplit_kernel<<<dim3(64, 64), 256>>>(W0, w0h, w0l, 2048, 2048);
    tsplit_kernel<<<dim3(64, 64), 256>>>(W1, w1h, w1l, 2048, 2048);
    tsplit_kernel<<<dim3(4, 64), 256>>>(W2, w2h, w2l, 2048, 128);

    // input split (both views into one M=8192 buffer)
    const int NSPLIT = (4096 * 2048 / 4) / 256;
    split_kernel<<<NSPLIT, 256>>>((const float4*)x1, (uint2*)xhi, (uint2*)xlo);
    split_kernel<<<NSPLIT, 256>>>((const float4*)x2,
                                  (uint2*)(xhi + (long)4096 * 2048),
                                  (uint2*)(xlo + (long)4096 * 2048));

    // batched MLP over M=8192
    dim3 gG(64, 16);
    gemm_mma<true, true><<<gG, 256, GEMM_SMEM>>>(
        xhi, xlo, w0h, w0l, b0, a0h, a0l, (float*)0);
    gemm_mma<false, true><<<gG, 256, GEMM_SMEM>>>(
        a0h, a0l, w1h, w1l, b1, a1h, a1l, (float*)0);
    gemm_head<<<dim3(1, 128), 256, HEAD_SMEM>>>(a1h, a1l, w2h, w2l, b2, feat);

    normalize_kernel<<<1024, 256>>>(feat, fhi, flo);
    pos_kernel<<<1024, 256>>>(feat, pos, S);
    loss_mma<<<dim3(2, 64), 256, LOSS_SMEM>>>(fhi, flo, S);
    final_kernel<<<1, 256>>>(S, pos, out);
}